// round 2
// baseline (speedup 1.0000x reference)
#include <cuda_runtime.h>
#include <cstdint>
#include <cstddef>

#define BATCH 4
#define C_IN 256
#define C_I 128
#define HH 96
#define WW 96
#define HW 9216
#define PH 47
#define M_VALID 2209
#define M_PAD 2240
#define N_MTILES 35   // ceil(2209/64)

// ---------------- scratch (device globals; zero-initialized, incl. pads) ----
__device__ float d_conv[(size_t)3 * BATCH * C_I * HW];   // [head][b][ci][hw]
__device__ float d_gT[(size_t)BATCH * M_PAD * C_I];      // [b][m][ci]
__device__ float d_phiP[(size_t)BATCH * C_I * M_PAD];    // [b][ci][m]
__device__ float d_yT[(size_t)BATCH * HW * C_I];         // [b][n][ci]

// ---------------- kernel 1: fused g/theta/phi 1x1 conv (SGEMM) --------------
// grid (144, 6, 4): x = 64-col tile of HW, y = 6 row-tiles of 384 stacked
// out-channels (head = y>>1), z = batch. 64x64 tile, K=256, 4x4 per thread.
__global__ __launch_bounds__(256) void k_conv3(
    const float* __restrict__ x,
    const float* __restrict__ gw, const float* __restrict__ gb,
    const float* __restrict__ tw, const float* __restrict__ tb,
    const float* __restrict__ pw, const float* __restrict__ pb)
{
    __shared__ float As[16][64];
    __shared__ float Bs[16][64];
    const int t  = threadIdx.x;
    const int ty = t >> 4, tx = t & 15;
    const int col0 = blockIdx.x * 64;
    const int by   = blockIdx.y;
    const int b    = blockIdx.z;
    const int head = by >> 1;
    const int sub  = by & 1;
    const float* Wp = (head == 0) ? gw : (head == 1 ? tw : pw);
    const float* Bp = (head == 0) ? gb : (head == 1 ? tb : pb);
    const float* xb = x + (size_t)b * C_IN * HW;

    const int ar = (t * 4) >> 4;   // A: row in tile (0..63)
    const int ak = (t * 4) & 15;   // A: k offset (0,4,8,12)
    const int bk = (t * 4) >> 6;   // B: k row (0..15)
    const int bc = (t * 4) & 63;   // B: col (0..60 step 4)

    float acc[4][4] = {};
    for (int k0 = 0; k0 < 256; k0 += 16) {
        float4 av = *(const float4*)(Wp + (size_t)(sub * 64 + ar) * 256 + k0 + ak);
        As[ak + 0][ar] = av.x; As[ak + 1][ar] = av.y;
        As[ak + 2][ar] = av.z; As[ak + 3][ar] = av.w;
        *(float4*)(&Bs[bk][bc]) =
            *(const float4*)(xb + (size_t)(k0 + bk) * HW + col0 + bc);
        __syncthreads();
#pragma unroll
        for (int kk = 0; kk < 16; ++kk) {
            float4 a4 = *(float4*)(&As[kk][ty * 4]);
            float4 b4 = *(float4*)(&Bs[kk][tx * 4]);
            float av_[4] = {a4.x, a4.y, a4.z, a4.w};
            float bv_[4] = {b4.x, b4.y, b4.z, b4.w};
#pragma unroll
            for (int i = 0; i < 4; ++i)
#pragma unroll
                for (int j = 0; j < 4; ++j)
                    acc[i][j] += av_[i] * bv_[j];
        }
        __syncthreads();
    }
    float* outp = d_conv + ((size_t)(head * BATCH + b) * C_I + sub * 64) * HW;
#pragma unroll
    for (int i = 0; i < 4; ++i) {
        float bias = Bp[sub * 64 + ty * 4 + i];
        float4 v = make_float4(acc[i][0] + bias, acc[i][1] + bias,
                               acc[i][2] + bias, acc[i][3] + bias);
        *(float4*)(outp + (size_t)(ty * 4 + i) * HW + col0 + tx * 4) = v;
    }
}

// ---------------- kernel 2: 3x3/2 maxpool for g and phi ---------------------
__global__ void k_pool()
{
    int idx = blockIdx.x * blockDim.x + threadIdx.x;
    const int total = 2 * BATCH * C_I * M_VALID;
    if (idx >= total) return;
    int m = idx % M_VALID; int r1 = idx / M_VALID;
    int o = r1 % C_I;      int r2 = r1 / C_I;
    int b = r2 % BATCH;    int which = r2 / BATCH;   // 0 = g, 1 = phi
    int head = which ? 2 : 0;
    const float* src = d_conv + ((size_t)(head * BATCH + b) * C_I + o) * HW;
    int pr = m / PH, pc = m % PH;
    const float* p = src + (pr * 2) * WW + pc * 2;
    float v = p[0];
    v = fmaxf(v, p[1]); v = fmaxf(v, p[2]);
    v = fmaxf(v, p[WW]); v = fmaxf(v, p[WW + 1]); v = fmaxf(v, p[WW + 2]);
    v = fmaxf(v, p[2 * WW]); v = fmaxf(v, p[2 * WW + 1]); v = fmaxf(v, p[2 * WW + 2]);
    if (which == 0) d_gT[((size_t)b * M_PAD + m) * C_I + o] = v;
    else            d_phiP[((size_t)b * C_I + o) * M_PAD + m] = v;
}

// ---------------- kernel 3: flash attention ---------------------------------
// grid (144, 4): x = 64-row query tile, y = batch. 256 threads.
// smem: thT [128d][64n] | phs [128d][64m] | gs [64m][128d] | Ps [64n][68]
__global__ __launch_bounds__(256) void k_attn()
{
    extern __shared__ float sm[];
    float* thT = sm;             // 8192
    float* phs = sm + 8192;      // 8192
    float* gs  = sm + 16384;     // 8192
    float* Ps  = sm + 24576;     // 64*68 = 4352
    const int t  = threadIdx.x;
    const int ty = t >> 4, tx = t & 15;
    const int b  = blockIdx.y;
    const int n0 = blockIdx.x * 64;

    const float* thbase = d_conv + ((size_t)(1 * BATCH + b) * C_I) * HW + n0;
    for (int e = t * 4; e < 8192; e += 1024) {
        int dd = e >> 6, n = e & 63;
        *(float4*)(thT + dd * 64 + n) =
            *(const float4*)(thbase + (size_t)dd * HW + n);
    }
    const float* phbase = d_phiP + (size_t)b * C_I * M_PAD;
    const float* gbase  = d_gT + (size_t)b * M_PAD * C_I;

    float mrow[4], lrow[4], O[4][8];
#pragma unroll
    for (int i = 0; i < 4; ++i) {
        mrow[i] = -1e30f; lrow[i] = 0.f;
#pragma unroll
        for (int j = 0; j < 8; ++j) O[i][j] = 0.f;
    }

    for (int mt = 0; mt < N_MTILES; ++mt) {
        const int m0 = mt * 64;
        for (int e = t * 4; e < 8192; e += 1024) {
            int dd = e >> 6, m = e & 63;
            *(float4*)(phs + dd * 64 + m) =
                *(const float4*)(phbase + (size_t)dd * M_PAD + m0 + m);
        }
        __syncthreads();

        float S[4][4] = {};
#pragma unroll 8
        for (int kk = 0; kk < 128; ++kk) {
            float4 a4 = *(float4*)(thT + kk * 64 + ty * 4);
            float4 b4 = *(float4*)(phs + kk * 64 + tx * 4);
            float av_[4] = {a4.x, a4.y, a4.z, a4.w};
            float bv_[4] = {b4.x, b4.y, b4.z, b4.w};
#pragma unroll
            for (int i = 0; i < 4; ++i)
#pragma unroll
                for (int j = 0; j < 4; ++j)
                    S[i][j] += av_[i] * bv_[j];
        }
#pragma unroll
        for (int j = 0; j < 4; ++j)
            if (m0 + tx * 4 + j >= M_VALID) {
                S[0][j] = -1e30f; S[1][j] = -1e30f;
                S[2][j] = -1e30f; S[3][j] = -1e30f;
            }
        // online softmax over the 16 threads sharing each row (tx group)
        float alpha[4];
#pragma unroll
        for (int i = 0; i < 4; ++i) {
            float rx = fmaxf(fmaxf(S[i][0], S[i][1]), fmaxf(S[i][2], S[i][3]));
            rx = fmaxf(rx, __shfl_xor_sync(0xffffffffu, rx, 1));
            rx = fmaxf(rx, __shfl_xor_sync(0xffffffffu, rx, 2));
            rx = fmaxf(rx, __shfl_xor_sync(0xffffffffu, rx, 4));
            rx = fmaxf(rx, __shfl_xor_sync(0xffffffffu, rx, 8));
            float mn = fmaxf(mrow[i], rx);
            alpha[i] = __expf(mrow[i] - mn);
            mrow[i] = mn;
            float rs = 0.f;
#pragma unroll
            for (int j = 0; j < 4; ++j) { S[i][j] = __expf(S[i][j] - mn); rs += S[i][j]; }
            rs += __shfl_xor_sync(0xffffffffu, rs, 1);
            rs += __shfl_xor_sync(0xffffffffu, rs, 2);
            rs += __shfl_xor_sync(0xffffffffu, rs, 4);
            rs += __shfl_xor_sync(0xffffffffu, rs, 8);
            lrow[i] = lrow[i] * alpha[i] + rs;
#pragma unroll
            for (int j = 0; j < 8; ++j) O[i][j] *= alpha[i];
        }
        __syncthreads();   // previous Ps/gs consumers done
#pragma unroll
        for (int i = 0; i < 4; ++i)
            *(float4*)(Ps + (ty * 4 + i) * 68 + tx * 4) =
                make_float4(S[i][0], S[i][1], S[i][2], S[i][3]);
        for (int e = t * 4; e < 8192; e += 1024) {
            int m = e >> 7, dd = e & 127;
            *(float4*)(gs + m * 128 + dd) =
                *(const float4*)(gbase + (size_t)(m0 + m) * C_I + dd);
        }
        __syncthreads();
        // O += P @ G  (thread: 4 rows x 8 d-cols)
#pragma unroll 4
        for (int kk4 = 0; kk4 < 64; kk4 += 4) {
            float4 pA[4];
#pragma unroll
            for (int i = 0; i < 4; ++i)
                pA[i] = *(float4*)(Ps + (ty * 4 + i) * 68 + kk4);
#pragma unroll
            for (int s = 0; s < 4; ++s) {
                float4 g0 = *(float4*)(gs + (kk4 + s) * 128 + tx * 8);
                float4 g1 = *(float4*)(gs + (kk4 + s) * 128 + tx * 8 + 4);
                float gv[8] = {g0.x, g0.y, g0.z, g0.w, g1.x, g1.y, g1.z, g1.w};
                float pv[4] = {((const float*)&pA[0])[s], ((const float*)&pA[1])[s],
                               ((const float*)&pA[2])[s], ((const float*)&pA[3])[s]};
#pragma unroll
                for (int i = 0; i < 4; ++i)
#pragma unroll
                    for (int j = 0; j < 8; ++j)
                        O[i][j] += pv[i] * gv[j];
            }
        }
    }
    float* yb = d_yT + ((size_t)b * HW + n0) * C_I;
#pragma unroll
    for (int i = 0; i < 4; ++i) {
        float inv = 1.0f / lrow[i];
        float4 v0 = make_float4(O[i][0] * inv, O[i][1] * inv, O[i][2] * inv, O[i][3] * inv);
        float4 v1 = make_float4(O[i][4] * inv, O[i][5] * inv, O[i][6] * inv, O[i][7] * inv);
        *(float4*)(yb + (size_t)(ty * 4 + i) * C_I + tx * 8) = v0;
        *(float4*)(yb + (size_t)(ty * 4 + i) * C_I + tx * 8 + 4) = v1;
    }
}

// ---------------- kernel 4: W_y conv (K=128) + bias + residual --------------
// grid (144, 4, 4): x = 64-col tile, y = 64-row out-channel tile, z = batch.
__global__ __launch_bounds__(256) void k_out(
    const float* __restrict__ ww, const float* __restrict__ wb,
    const float* __restrict__ x, float* __restrict__ out)
{
    __shared__ float As[16][64];
    __shared__ float Bs[16][64];
    const int t  = threadIdx.x;
    const int ty = t >> 4, tx = t & 15;
    const int col0 = blockIdx.x * 64;
    const int row0 = blockIdx.y * 64;
    const int b    = blockIdx.z;
    const int ar = (t * 4) >> 4;   // 0..63
    const int ak = (t * 4) & 15;   // 0,4,8,12
    const float* yb = d_yT + (size_t)b * HW * C_I;

    float acc[4][4] = {};
    for (int k0 = 0; k0 < 128; k0 += 16) {
        float4 av = *(const float4*)(ww + (size_t)(row0 + ar) * C_I + k0 + ak);
        As[ak + 0][ar] = av.x; As[ak + 1][ar] = av.y;
        As[ak + 2][ar] = av.z; As[ak + 3][ar] = av.w;
        float4 bv = *(const float4*)(yb + (size_t)(col0 + ar) * C_I + k0 + ak);
        Bs[ak + 0][ar] = bv.x; Bs[ak + 1][ar] = bv.y;
        Bs[ak + 2][ar] = bv.z; Bs[ak + 3][ar] = bv.w;
        __syncthreads();
#pragma unroll
        for (int kk = 0; kk < 16; ++kk) {
            float4 a4 = *(float4*)(&As[kk][ty * 4]);
            float4 b4 = *(float4*)(&Bs[kk][tx * 4]);
            float av_[4] = {a4.x, a4.y, a4.z, a4.w};
            float bv_[4] = {b4.x, b4.y, b4.z, b4.w};
#pragma unroll
            for (int i = 0; i < 4; ++i)
#pragma unroll
                for (int j = 0; j < 4; ++j)
                    acc[i][j] += av_[i] * bv_[j];
        }
        __syncthreads();
    }
    const float* xb = x + ((size_t)b * C_IN + row0) * HW;
    float* ob = out + ((size_t)b * C_IN + row0) * HW;
#pragma unroll
    for (int i = 0; i < 4; ++i) {
        float bias = wb[row0 + ty * 4 + i];
        float4 xv = *(const float4*)(xb + (size_t)(ty * 4 + i) * HW + col0 + tx * 4);
        float4 v = make_float4(acc[i][0] + bias + xv.x, acc[i][1] + bias + xv.y,
                               acc[i][2] + bias + xv.z, acc[i][3] + bias + xv.w);
        *(float4*)(ob + (size_t)(ty * 4 + i) * HW + col0 + tx * 4) = v;
    }
}

// ---------------- launch ----------------------------------------------------
extern "C" void kernel_launch(void* const* d_in, const int* in_sizes, int n_in,
                              void* d_out, int out_size)
{
    const float* x  = (const float*)d_in[0];
    const float* gw = (const float*)d_in[1];
    const float* gb = (const float*)d_in[2];
    const float* tw = (const float*)d_in[3];
    const float* tb = (const float*)d_in[4];
    const float* pw = (const float*)d_in[5];
    const float* pb = (const float*)d_in[6];
    const float* ww = (const float*)d_in[7];
    const float* wb = (const float*)d_in[8];
    float* out = (float*)d_out;

    const int attn_smem = (8192 + 8192 + 8192 + 64 * 68) * 4;  // 115712 B
    cudaFuncSetAttribute(k_attn, cudaFuncAttributeMaxDynamicSharedMemorySize,
                         attn_smem);

    k_conv3<<<dim3(HW / 64, 6, BATCH), 256>>>(x, gw, gb, tw, tb, pw, pb);
    const int pool_total = 2 * BATCH * C_I * M_VALID;
    k_pool<<<(pool_total + 255) / 256, 256>>>();
    k_attn<<<dim3(HW / 64, BATCH), 256, attn_smem>>>();
    k_out<<<dim3(HW / 64, C_IN / 64, BATCH), 256>>>(ww, wb, x, out);
}

// round 5
// speedup vs baseline: 2.2717x; 2.2717x over previous
#include <cuda_runtime.h>
#include <cstdint>
#include <cstddef>

#define BATCH 4
#define C_IN 256
#define C_I 128
#define HH 96
#define WW 96
#define HW 9216
#define PH 47
#define M_VALID 2209
#define M_PAD 2240
#define N_MTILES 35        // 2240 / 64
#define TILE_N 128
#define TILE_M 64

// ---------------- scratch (device globals; zero-initialized) ----------------
__device__ float d_conv[(size_t)2 * BATCH * C_I * HW];   // [slot g/phi][b][ci][hw]
__device__ float d_thT[(size_t)BATCH * HW * C_I];        // [b][n][ci]  (theta, n-major)
__device__ float d_phiT[(size_t)BATCH * M_PAD * C_I];    // [b][m][ci]  (phi pooled)
__device__ float d_gT[(size_t)BATCH * M_PAD * C_I];      // [b][m][ci]  (g pooled)
__device__ float d_yT[(size_t)BATCH * HW * C_I];         // [b][n][ci]

// ---------------- mma.sync helpers (base sm_100: no tcgen05!) ---------------
__device__ __forceinline__ uint32_t f2tf(float f) {
    uint32_t u;
    asm("cvt.rna.tf32.f32 %0, %1;" : "=r"(u) : "f"(f));
    return u;
}
__device__ __forceinline__ void mma_tf32(float* d, const uint32_t* a,
                                         uint32_t b0, uint32_t b1) {
    asm volatile(
        "mma.sync.aligned.m16n8k8.row.col.f32.tf32.tf32.f32 "
        "{%0,%1,%2,%3}, {%4,%5,%6,%7}, {%8,%9}, {%0,%1,%2,%3};"
        : "+f"(d[0]), "+f"(d[1]), "+f"(d[2]), "+f"(d[3])
        : "r"(a[0]), "r"(a[1]), "r"(a[2]), "r"(a[3]), "r"(b0), "r"(b1));
}

// ---------------- kernel 1: fused g/theta/phi 1x1 conv (SGEMM) --------------
__global__ __launch_bounds__(256) void k_conv3(
    const float* __restrict__ x,
    const float* __restrict__ gw, const float* __restrict__ gb,
    const float* __restrict__ tw, const float* __restrict__ tb,
    const float* __restrict__ pw, const float* __restrict__ pb)
{
    __shared__ float As[16][64];
    __shared__ float Bs[16][64];
    const int t  = threadIdx.x;
    const int ty = t >> 4, tx = t & 15;
    const int col0 = blockIdx.x * 64;
    const int by   = blockIdx.y;
    const int b    = blockIdx.z;
    const int head = by >> 1;
    const int sub  = by & 1;
    const float* Wp = (head == 0) ? gw : (head == 1 ? tw : pw);
    const float* Bp = (head == 0) ? gb : (head == 1 ? tb : pb);
    const float* xb = x + (size_t)b * C_IN * HW;

    const int ar = (t * 4) >> 4;
    const int ak = (t * 4) & 15;
    const int bk = (t * 4) >> 6;
    const int bc = (t * 4) & 63;

    float acc[4][4] = {};
    for (int k0 = 0; k0 < 256; k0 += 16) {
        float4 av = *(const float4*)(Wp + (size_t)(sub * 64 + ar) * 256 + k0 + ak);
        As[ak + 0][ar] = av.x; As[ak + 1][ar] = av.y;
        As[ak + 2][ar] = av.z; As[ak + 3][ar] = av.w;
        *(float4*)(&Bs[bk][bc]) =
            *(const float4*)(xb + (size_t)(k0 + bk) * HW + col0 + bc);
        __syncthreads();
#pragma unroll
        for (int kk = 0; kk < 16; ++kk) {
            float4 a4 = *(float4*)(&As[kk][ty * 4]);
            float4 b4 = *(float4*)(&Bs[kk][tx * 4]);
            float av_[4] = {a4.x, a4.y, a4.z, a4.w};
            float bv_[4] = {b4.x, b4.y, b4.z, b4.w};
#pragma unroll
            for (int i = 0; i < 4; ++i)
#pragma unroll
                for (int j = 0; j < 4; ++j)
                    acc[i][j] += av_[i] * bv_[j];
        }
        __syncthreads();
    }
    if (head == 1) {
        // theta: write n-major [b][n][128]
        float* outp = d_thT + ((size_t)b * HW + col0) * C_I + sub * 64;
#pragma unroll
        for (int i = 0; i < 4; ++i) {
            float bias = Bp[sub * 64 + ty * 4 + i];
#pragma unroll
            for (int j = 0; j < 4; ++j)
                outp[(size_t)(tx * 4 + j) * C_I + ty * 4 + i] = acc[i][j] + bias;
        }
    } else {
        int slot = head >> 1;  // g -> 0, phi(head 2) -> 1
        float* outp = d_conv + ((size_t)(slot * BATCH + b) * C_I + sub * 64) * HW;
#pragma unroll
        for (int i = 0; i < 4; ++i) {
            float bias = Bp[sub * 64 + ty * 4 + i];
            float4 v = make_float4(acc[i][0] + bias, acc[i][1] + bias,
                                   acc[i][2] + bias, acc[i][3] + bias);
            *(float4*)(outp + (size_t)(ty * 4 + i) * HW + col0 + tx * 4) = v;
        }
    }
}

// ---------------- kernel 2: 3x3/2 maxpool for g and phi ---------------------
__global__ void k_pool()
{
    int idx = blockIdx.x * blockDim.x + threadIdx.x;
    const int total = 2 * BATCH * C_I * M_VALID;
    if (idx >= total) return;
    int m = idx % M_VALID; int r1 = idx / M_VALID;
    int o = r1 % C_I;      int r2 = r1 / C_I;
    int b = r2 % BATCH;    int which = r2 / BATCH;   // 0 = g, 1 = phi
    const float* src = d_conv + ((size_t)(which * BATCH + b) * C_I + o) * HW;
    int pr = m / PH, pc = m % PH;
    const float* p = src + (pr * 2) * WW + pc * 2;
    float v = p[0];
    v = fmaxf(v, p[1]); v = fmaxf(v, p[2]);
    v = fmaxf(v, p[WW]); v = fmaxf(v, p[WW + 1]); v = fmaxf(v, p[WW + 2]);
    v = fmaxf(v, p[2 * WW]); v = fmaxf(v, p[2 * WW + 1]); v = fmaxf(v, p[2 * WW + 2]);
    if (which == 0) d_gT[((size_t)b * M_PAD + m) * C_I + o] = v;
    else            d_phiT[((size_t)b * M_PAD + m) * C_I + o] = v;
}

// ---------------- kernel 3: mma.sync tf32 flash attention -------------------
// grid (72, 4), 256 threads / 8 warps. Warp w owns query rows [w*16, w*16+16).
// smem (uint32/tf32 words): phi [64m][132] | g [64m][132] | P [128n][68]
#define PHI_S 0
#define G_S   8448
#define P_S   16896
#define ATTN_SMEM_WORDS (16896 + 128 * 68)
#define ATTN_SMEM_BYTES (ATTN_SMEM_WORDS * 4)

__global__ __launch_bounds__(256, 1) void k_attn()
{
    extern __shared__ uint32_t sm[];
    uint32_t* phi_s = sm + PHI_S;
    uint32_t* g_s   = sm + G_S;
    uint32_t* p_s   = sm + P_S;

    const int t    = threadIdx.x;
    const int w    = t >> 5;
    const int lane = t & 31;
    const int g    = lane >> 2;    // group id 0..7
    const int tg   = lane & 3;     // thread-in-group 0..3
    const int rw   = w * 16;       // warp's first query row in tile
    const int b    = blockIdx.y;
    const int n0   = blockIdx.x * TILE_N;

    // --- theta fragments: [16 rows][k=128], cvt to tf32 once, live all loop --
    uint32_t aF[16][4];
    {
        const float* thp = d_thT + ((size_t)b * HW + n0 + rw) * C_I;
#pragma unroll
        for (int kc = 0; kc < 16; ++kc) {
            aF[kc][0] = f2tf(thp[(size_t)g * C_I + kc * 8 + tg]);
            aF[kc][1] = f2tf(thp[(size_t)(g + 8) * C_I + kc * 8 + tg]);
            aF[kc][2] = f2tf(thp[(size_t)g * C_I + kc * 8 + tg + 4]);
            aF[kc][3] = f2tf(thp[(size_t)(g + 8) * C_I + kc * 8 + tg + 4]);
        }
    }

    float o[16][4];
#pragma unroll
    for (int dt = 0; dt < 16; ++dt) {
        o[dt][0] = 0.f; o[dt][1] = 0.f; o[dt][2] = 0.f; o[dt][3] = 0.f;
    }
    float l0 = 0.f, l1 = 0.f, off0 = 0.f, off1 = 0.f;

    const float* psrc = d_phiT + (size_t)b * M_PAD * C_I;
    const float* gsrc = d_gT + (size_t)b * M_PAD * C_I;

    for (int mt = 0; mt < N_MTILES; ++mt) {
        const int m0 = mt * TILE_M;
        __syncthreads();   // previous tile's smem consumers finished
        // load phi + g tiles (64 rows x 128), cvt to tf32 on store
#pragma unroll
        for (int it = 0; it < 8; ++it) {
            int idx = t + it * 256;
            int r = idx >> 5, c = (idx & 31) * 4;
            float4 v = *(const float4*)(psrc + (size_t)(m0 + r) * C_I + c);
            uint4 u = make_uint4(f2tf(v.x), f2tf(v.y), f2tf(v.z), f2tf(v.w));
            *(uint4*)(phi_s + r * 132 + c) = u;
            float4 vg = *(const float4*)(gsrc + (size_t)(m0 + r) * C_I + c);
            uint4 ug = make_uint4(f2tf(vg.x), f2tf(vg.y), f2tf(vg.z), f2tf(vg.w));
            *(uint4*)(g_s + r * 132 + c) = ug;
        }
        __syncthreads();

        // ---- MMA1: S[16 x 64] = theta . phi^T -------------------------------
        float s[8][4];
#pragma unroll
        for (int j = 0; j < 8; ++j) {
            s[j][0] = 0.f; s[j][1] = 0.f; s[j][2] = 0.f; s[j][3] = 0.f;
        }
#pragma unroll
        for (int kc = 0; kc < 16; ++kc) {
#pragma unroll
            for (int j = 0; j < 8; ++j) {
                uint32_t b0 = phi_s[(j * 8 + g) * 132 + kc * 8 + tg];
                uint32_t b1 = phi_s[(j * 8 + g) * 132 + kc * 8 + tg + 4];
                mma_tf32(s[j], aF[kc], b0, b1);
            }
        }

        // ---- softmax with fixed per-row offset ------------------------------
        if (mt == 0) {
            float mx0 = s[0][0], mx1 = s[0][2];
#pragma unroll
            for (int j = 0; j < 8; ++j) {
                mx0 = fmaxf(mx0, fmaxf(s[j][0], s[j][1]));
                mx1 = fmaxf(mx1, fmaxf(s[j][2], s[j][3]));
            }
            mx0 = fmaxf(mx0, __shfl_xor_sync(0xffffffffu, mx0, 1));
            mx0 = fmaxf(mx0, __shfl_xor_sync(0xffffffffu, mx0, 2));
            mx1 = fmaxf(mx1, __shfl_xor_sync(0xffffffffu, mx1, 1));
            mx1 = fmaxf(mx1, __shfl_xor_sync(0xffffffffu, mx1, 2));
            off0 = mx0 + 25.0f;
            off1 = mx1 + 25.0f;
        }
        const bool lastt = (mt == N_MTILES - 1);
#pragma unroll
        for (int j = 0; j < 8; ++j) {
            float e00 = __expf(s[j][0] - off0);
            float e01 = __expf(s[j][1] - off0);
            float e10 = __expf(s[j][2] - off1);
            float e11 = __expf(s[j][3] - off1);
            if (lastt) {
                int mcol = m0 + j * 8 + 2 * tg;
                if (mcol >= M_VALID)     { e00 = 0.f; e10 = 0.f; }
                if (mcol + 1 >= M_VALID) { e01 = 0.f; e11 = 0.f; }
            }
            l0 += e00 + e01;
            l1 += e10 + e11;
            *(uint2*)(p_s + (rw + g) * 68 + j * 8 + 2 * tg) =
                make_uint2(f2tf(e00), f2tf(e01));
            *(uint2*)(p_s + (rw + g + 8) * 68 + j * 8 + 2 * tg) =
                make_uint2(f2tf(e10), f2tf(e11));
        }
        __syncwarp();   // warp-private P slice: visible to own warp

        // ---- MMA2: O[16 x 128] += P . g ------------------------------------
#pragma unroll
        for (int kc2 = 0; kc2 < 8; ++kc2) {
            uint32_t pa[4];
            pa[0] = p_s[(rw + g) * 68 + kc2 * 8 + tg];
            pa[1] = p_s[(rw + g + 8) * 68 + kc2 * 8 + tg];
            pa[2] = p_s[(rw + g) * 68 + kc2 * 8 + tg + 4];
            pa[3] = p_s[(rw + g + 8) * 68 + kc2 * 8 + tg + 4];
#pragma unroll
            for (int dt = 0; dt < 16; ++dt) {
                uint32_t b0 = g_s[(kc2 * 8 + tg) * 132 + dt * 8 + g];
                uint32_t b1 = g_s[(kc2 * 8 + tg + 4) * 132 + dt * 8 + g];
                mma_tf32(o[dt], pa, b0, b1);
            }
        }
    }

    // ---- finalize: normalize and store y -----------------------------------
    l0 += __shfl_xor_sync(0xffffffffu, l0, 1);
    l0 += __shfl_xor_sync(0xffffffffu, l0, 2);
    l1 += __shfl_xor_sync(0xffffffffu, l1, 1);
    l1 += __shfl_xor_sync(0xffffffffu, l1, 2);
    const float inv0 = 1.0f / l0;
    const float inv1 = 1.0f / l1;
    float* yr0 = d_yT + ((size_t)b * HW + n0 + rw + g) * C_I;
    float* yr1 = d_yT + ((size_t)b * HW + n0 + rw + g + 8) * C_I;
#pragma unroll
    for (int dt = 0; dt < 16; ++dt) {
        *(float2*)(yr0 + dt * 8 + 2 * tg) =
            make_float2(o[dt][0] * inv0, o[dt][1] * inv0);
        *(float2*)(yr1 + dt * 8 + 2 * tg) =
            make_float2(o[dt][2] * inv1, o[dt][3] * inv1);
    }
}

// ---------------- kernel 4: W_y conv (K=128) + bias + residual --------------
__global__ __launch_bounds__(256) void k_out(
    const float* __restrict__ ww, const float* __restrict__ wb,
    const float* __restrict__ x, float* __restrict__ out)
{
    __shared__ float As[16][64];
    __shared__ float Bs[16][64];
    const int t  = threadIdx.x;
    const int ty = t >> 4, tx = t & 15;
    const int col0 = blockIdx.x * 64;
    const int row0 = blockIdx.y * 64;
    const int b    = blockIdx.z;
    const int ar = (t * 4) >> 4;
    const int ak = (t * 4) & 15;
    const float* yb = d_yT + (size_t)b * HW * C_I;

    float acc[4][4] = {};
    for (int k0 = 0; k0 < 128; k0 += 16) {
        float4 av = *(const float4*)(ww + (size_t)(row0 + ar) * C_I + k0 + ak);
        As[ak + 0][ar] = av.x; As[ak + 1][ar] = av.y;
        As[ak + 2][ar] = av.z; As[ak + 3][ar] = av.w;
        float4 bv = *(const float4*)(yb + (size_t)(col0 + ar) * C_I + k0 + ak);
        Bs[ak + 0][ar] = bv.x; Bs[ak + 1][ar] = bv.y;
        Bs[ak + 2][ar] = bv.z; Bs[ak + 3][ar] = bv.w;
        __syncthreads();
#pragma unroll
        for (int kk = 0; kk < 16; ++kk) {
            float4 a4 = *(float4*)(&As[kk][ty * 4]);
            float4 b4 = *(float4*)(&Bs[kk][tx * 4]);
            float av_[4] = {a4.x, a4.y, a4.z, a4.w};
            float bv_[4] = {b4.x, b4.y, b4.z, b4.w};
#pragma unroll
            for (int i = 0; i < 4; ++i)
#pragma unroll
                for (int j = 0; j < 4; ++j)
                    acc[i][j] += av_[i] * bv_[j];
        }
        __syncthreads();
    }
    const float* xb = x + ((size_t)b * C_IN + row0) * HW;
    float* ob = out + ((size_t)b * C_IN + row0) * HW;
#pragma unroll
    for (int i = 0; i < 4; ++i) {
        float bias = wb[row0 + ty * 4 + i];
        float4 xv = *(const float4*)(xb + (size_t)(ty * 4 + i) * HW + col0 + tx * 4);
        float4 v = make_float4(acc[i][0] + bias + xv.x, acc[i][1] + bias + xv.y,
                               acc[i][2] + bias + xv.z, acc[i][3] + bias + xv.w);
        *(float4*)(ob + (size_t)(ty * 4 + i) * HW + col0 + tx * 4) = v;
    }
}

// ---------------- launch ----------------------------------------------------
extern "C" void kernel_launch(void* const* d_in, const int* in_sizes, int n_in,
                              void* d_out, int out_size)
{
    const float* x  = (const float*)d_in[0];
    const float* gw = (const float*)d_in[1];
    const float* gb = (const float*)d_in[2];
    const float* tw = (const float*)d_in[3];
    const float* tb = (const float*)d_in[4];
    const float* pw = (const float*)d_in[5];
    const float* pb = (const float*)d_in[6];
    const float* ww = (const float*)d_in[7];
    const float* wb = (const float*)d_in[8];
    float* out = (float*)d_out;

    cudaFuncSetAttribute(k_attn, cudaFuncAttributeMaxDynamicSharedMemorySize,
                         ATTN_SMEM_BYTES);

    k_conv3<<<dim3(HW / 64, 6, BATCH), 256>>>(x, gw, gb, tw, tb, pw, pb);
    const int pool_total = 2 * BATCH * C_I * M_VALID;
    k_pool<<<(pool_total + 255) / 256, 256>>>();
    k_attn<<<dim3(HW / TILE_N, BATCH), 256, ATTN_SMEM_BYTES>>>();
    k_out<<<dim3(HW / 64, C_IN / 64, BATCH), 256>>>(ww, wb, x, out);
}

// round 6
// speedup vs baseline: 3.8860x; 1.7106x over previous
#include <cuda_runtime.h>
#include <cstdint>
#include <cstddef>

#define BATCH 4
#define C_IN 256
#define C_I 128
#define HH 96
#define WW 96
#define HW 9216
#define PH 47
#define M_VALID 2209
#define M_PAD 2240
#define N_MTILES 35        // 2240 / 64
#define TILE_N 128
#define TILE_M 64

// ---------------- scratch (device globals; zero-initialized) ----------------
__device__ float d_conv[(size_t)3 * BATCH * C_I * HW];   // [g|theta|phi][b][ci][hw]
__device__ float d_phiT[(size_t)BATCH * M_PAD * C_I];    // [b][m][ci]  (phi pooled)
__device__ float d_gP[(size_t)BATCH * C_I * M_PAD];      // [b][ci][m]  (g pooled)
__device__ float d_yT[(size_t)BATCH * HW * C_I];         // [b][n][ci]

// ---------------- mma.sync helpers (base sm_100 target) ---------------------
__device__ __forceinline__ uint32_t f2tf(float f) {
    uint32_t u;
    asm("cvt.rna.tf32.f32 %0, %1;" : "=r"(u) : "f"(f));
    return u;
}
__device__ __forceinline__ void mma_tf32(float* d, const uint32_t* a,
                                         uint32_t b0, uint32_t b1) {
    asm volatile(
        "mma.sync.aligned.m16n8k8.row.col.f32.tf32.tf32.f32 "
        "{%0,%1,%2,%3}, {%4,%5,%6,%7}, {%8,%9}, {%0,%1,%2,%3};"
        : "+f"(d[0]), "+f"(d[1]), "+f"(d[2]), "+f"(d[3])
        : "r"(a[0]), "r"(a[1]), "r"(a[2]), "r"(a[3]), "r"(b0), "r"(b1));
}

// ---------------- kernel 1: fused g/theta/phi conv, tf32 mma ----------------
// grid (72, 3, 4): x = 128-col spatial tile, y = head (g/theta/phi), z = batch.
// CTA 256 thr / 8 warps; warp tile 32 rows x 64 cols. K = 256 in chunks of 32.
__global__ __launch_bounds__(256, 2) void k_conv3(
    const float* __restrict__ x,
    const float* __restrict__ gw, const float* __restrict__ gb,
    const float* __restrict__ tw, const float* __restrict__ tb,
    const float* __restrict__ pw, const float* __restrict__ pb)
{
    __shared__ uint32_t Ws[128 * 36];   // [row][k] stride 36
    __shared__ uint32_t Xs[32 * 128];   // [k][n] stride 128, XOR-swizzled cols

    const int t    = threadIdx.x;
    const int w    = t >> 5;
    const int lane = t & 31;
    const int g    = lane >> 2;
    const int tg   = lane & 3;
    const int rw   = (w & 3) * 32;
    const int cw   = (w >> 2) * 64;
    const int n0   = blockIdx.x * 128;
    const int head = blockIdx.y;
    const int b    = blockIdx.z;
    const float* Wp = (head == 0) ? gw : (head == 1 ? tw : pw);
    const float* Bp = (head == 0) ? gb : (head == 1 ? tb : pb);
    const float* xb = x + (size_t)b * C_IN * HW;

    float o[2][8][4];
#pragma unroll
    for (int rt = 0; rt < 2; ++rt)
#pragma unroll
        for (int nt = 0; nt < 8; ++nt) {
            o[rt][nt][0] = 0.f; o[rt][nt][1] = 0.f;
            o[rt][nt][2] = 0.f; o[rt][nt][3] = 0.f;
        }

    for (int k0 = 0; k0 < 256; k0 += 32) {
        __syncthreads();
        // W chunk: 128 rows x 32 k
#pragma unroll
        for (int it = 0; it < 4; ++it) {
            int f4 = t + it * 256;
            int r = f4 >> 3, c = (f4 & 7) * 4;
            float4 v = *(const float4*)(Wp + (size_t)r * 256 + k0 + c);
            Ws[r * 36 + c + 0] = f2tf(v.x); Ws[r * 36 + c + 1] = f2tf(v.y);
            Ws[r * 36 + c + 2] = f2tf(v.z); Ws[r * 36 + c + 3] = f2tf(v.w);
        }
        // X chunk: 32 k x 128 n, XOR swizzle col by (k&3)<<3
#pragma unroll
        for (int it = 0; it < 4; ++it) {
            int f4 = t + it * 256;
            int r = f4 >> 5, c = (f4 & 31) * 4;
            int cs = c ^ ((r & 3) << 3);
            float4 v = *(const float4*)(xb + (size_t)(k0 + r) * HW + n0 + c);
            Xs[r * 128 + cs + 0] = f2tf(v.x); Xs[r * 128 + cs + 1] = f2tf(v.y);
            Xs[r * 128 + cs + 2] = f2tf(v.z); Xs[r * 128 + cs + 3] = f2tf(v.w);
        }
        __syncthreads();
#pragma unroll
        for (int ks = 0; ks < 4; ++ks) {
            uint32_t a[2][4];
#pragma unroll
            for (int rt = 0; rt < 2; ++rt) {
                int rbase = rw + rt * 16 + g;
                a[rt][0] = Ws[rbase * 36 + ks * 8 + tg];
                a[rt][1] = Ws[(rbase + 8) * 36 + ks * 8 + tg];
                a[rt][2] = Ws[rbase * 36 + ks * 8 + tg + 4];
                a[rt][3] = Ws[(rbase + 8) * 36 + ks * 8 + tg + 4];
            }
#pragma unroll
            for (int nt = 0; nt < 8; ++nt) {
                int col = (cw + nt * 8 + g) ^ (tg << 3);
                uint32_t b0 = Xs[(ks * 8 + tg) * 128 + col];
                uint32_t b1 = Xs[(ks * 8 + tg + 4) * 128 + col];
                mma_tf32(o[0][nt], a[0], b0, b1);
                mma_tf32(o[1][nt], a[1], b0, b1);
            }
        }
    }
    // epilogue: bias, write [ci][hw]
    float* outp = d_conv + ((size_t)(head * BATCH + b) * C_I) * HW;
#pragma unroll
    for (int rt = 0; rt < 2; ++rt) {
        int r0 = rw + rt * 16 + g;
        float bi0 = Bp[r0], bi1 = Bp[r0 + 8];
#pragma unroll
        for (int nt = 0; nt < 8; ++nt) {
            int col = n0 + cw + nt * 8 + 2 * tg;
            *(float2*)(outp + (size_t)r0 * HW + col) =
                make_float2(o[rt][nt][0] + bi0, o[rt][nt][1] + bi0);
            *(float2*)(outp + (size_t)(r0 + 8) * HW + col) =
                make_float2(o[rt][nt][2] + bi1, o[rt][nt][3] + bi1);
        }
    }
}

// ---------------- kernel 2: 3x3/2 maxpool for g and phi ---------------------
__global__ void k_pool()
{
    int idx = blockIdx.x * blockDim.x + threadIdx.x;
    const int total = 2 * BATCH * C_I * M_VALID;
    if (idx >= total) return;
    int m = idx % M_VALID; int r1 = idx / M_VALID;
    int o = r1 % C_I;      int r2 = r1 / C_I;
    int b = r2 % BATCH;    int which = r2 / BATCH;   // 0 = g, 1 = phi
    int slot = which ? 2 : 0;
    const float* src = d_conv + ((size_t)(slot * BATCH + b) * C_I + o) * HW;
    int pr = m / PH, pc = m % PH;
    const float* p = src + (pr * 2) * WW + pc * 2;
    float v = p[0];
    v = fmaxf(v, p[1]); v = fmaxf(v, p[2]);
    v = fmaxf(v, p[WW]); v = fmaxf(v, p[WW + 1]); v = fmaxf(v, p[WW + 2]);
    v = fmaxf(v, p[2 * WW]); v = fmaxf(v, p[2 * WW + 1]); v = fmaxf(v, p[2 * WW + 2]);
    if (which == 0) d_gP[((size_t)b * C_I + o) * M_PAD + m] = v;
    else            d_phiT[((size_t)b * M_PAD + m) * C_I + o] = v;
}

// ---------------- kernel 3: mma.sync tf32 flash attention -------------------
// grid (72, 4), 256 threads / 8 warps. Warp w owns query rows [w*16, w*16+16).
// smem words: phi [64m][132] | gT [128d][68] | P [128n][68]
#define PHI_S 0
#define G_S   8448
#define P_S   17152
#define ATTN_SMEM_WORDS (17152 + 128 * 68)
#define ATTN_SMEM_BYTES (ATTN_SMEM_WORDS * 4)

__global__ __launch_bounds__(256, 1) void k_attn()
{
    extern __shared__ uint32_t sm[];
    uint32_t* phi_s = sm + PHI_S;
    uint32_t* g_s   = sm + G_S;
    uint32_t* p_s   = sm + P_S;

    const int t    = threadIdx.x;
    const int w    = t >> 5;
    const int lane = t & 31;
    const int g    = lane >> 2;
    const int tg   = lane & 3;
    const int rw   = w * 16;
    const int b    = blockIdx.y;
    const int n0   = blockIdx.x * TILE_N;

    // theta fragments from [ci][hw] layout, tf32 once, held in regs
    uint32_t aF[16][4];
    {
        const float* thp = d_conv + ((size_t)(1 * BATCH + b) * C_I) * HW + n0 + rw;
#pragma unroll
        for (int kc = 0; kc < 16; ++kc) {
            aF[kc][0] = f2tf(thp[(size_t)(kc * 8 + tg) * HW + g]);
            aF[kc][1] = f2tf(thp[(size_t)(kc * 8 + tg) * HW + g + 8]);
            aF[kc][2] = f2tf(thp[(size_t)(kc * 8 + tg + 4) * HW + g]);
            aF[kc][3] = f2tf(thp[(size_t)(kc * 8 + tg + 4) * HW + g + 8]);
        }
    }

    float o[16][4];
#pragma unroll
    for (int dt = 0; dt < 16; ++dt) {
        o[dt][0] = 0.f; o[dt][1] = 0.f; o[dt][2] = 0.f; o[dt][3] = 0.f;
    }
    float l0 = 0.f, l1 = 0.f, off0 = 0.f, off1 = 0.f;

    const float* psrc = d_phiT + (size_t)b * M_PAD * C_I;
    const float* gsrc = d_gP + (size_t)b * C_I * M_PAD;

    for (int mt = 0; mt < N_MTILES; ++mt) {
        const int m0 = mt * TILE_M;
        __syncthreads();
        // phi tile [64 m][128 d] -> [m][ci] stride 132
#pragma unroll
        for (int it = 0; it < 8; ++it) {
            int f4 = t + it * 256;
            int r = f4 >> 5, c = (f4 & 31) * 4;
            float4 v = *(const float4*)(psrc + (size_t)(m0 + r) * C_I + c);
            phi_s[r * 132 + c + 0] = f2tf(v.x); phi_s[r * 132 + c + 1] = f2tf(v.y);
            phi_s[r * 132 + c + 2] = f2tf(v.z); phi_s[r * 132 + c + 3] = f2tf(v.w);
        }
        // g tile transposed: [128 d][64 m] stride 68 (from [ci][m] gmem)
#pragma unroll
        for (int it = 0; it < 8; ++it) {
            int f4 = t + it * 256;
            int r = f4 >> 4, c = (f4 & 15) * 4;
            float4 v = *(const float4*)(gsrc + (size_t)r * M_PAD + m0 + c);
            g_s[r * 68 + c + 0] = f2tf(v.x); g_s[r * 68 + c + 1] = f2tf(v.y);
            g_s[r * 68 + c + 2] = f2tf(v.z); g_s[r * 68 + c + 3] = f2tf(v.w);
        }
        __syncthreads();

        // ---- MMA1: S[16 x 64] = theta . phi^T -------------------------------
        float s[8][4];
#pragma unroll
        for (int j = 0; j < 8; ++j) {
            s[j][0] = 0.f; s[j][1] = 0.f; s[j][2] = 0.f; s[j][3] = 0.f;
        }
#pragma unroll
        for (int kc = 0; kc < 16; ++kc) {
#pragma unroll
            for (int j = 0; j < 8; ++j) {
                uint32_t b0 = phi_s[(j * 8 + g) * 132 + kc * 8 + tg];
                uint32_t b1 = phi_s[(j * 8 + g) * 132 + kc * 8 + tg + 4];
                mma_tf32(s[j], aF[kc], b0, b1);
            }
        }

        // ---- softmax, fixed per-row offset from tile-0 sample max ----------
        if (mt == 0) {
            float mx0 = s[0][0], mx1 = s[0][2];
#pragma unroll
            for (int j = 0; j < 8; ++j) {
                mx0 = fmaxf(mx0, fmaxf(s[j][0], s[j][1]));
                mx1 = fmaxf(mx1, fmaxf(s[j][2], s[j][3]));
            }
            mx0 = fmaxf(mx0, __shfl_xor_sync(0xffffffffu, mx0, 1));
            mx0 = fmaxf(mx0, __shfl_xor_sync(0xffffffffu, mx0, 2));
            mx1 = fmaxf(mx1, __shfl_xor_sync(0xffffffffu, mx1, 1));
            mx1 = fmaxf(mx1, __shfl_xor_sync(0xffffffffu, mx1, 2));
            off0 = mx0 + 25.0f;
            off1 = mx1 + 25.0f;
        }
        const bool lastt = (mt == N_MTILES - 1);
#pragma unroll
        for (int j = 0; j < 8; ++j) {
            float e00 = __expf(s[j][0] - off0);
            float e01 = __expf(s[j][1] - off0);
            float e10 = __expf(s[j][2] - off1);
            float e11 = __expf(s[j][3] - off1);
            if (lastt) {
                int mcol = m0 + j * 8 + 2 * tg;
                if (mcol >= M_VALID)     { e00 = 0.f; e10 = 0.f; }
                if (mcol + 1 >= M_VALID) { e01 = 0.f; e11 = 0.f; }
            }
            l0 += e00 + e01;
            l1 += e10 + e11;
            *(uint2*)(p_s + (rw + g) * 68 + j * 8 + 2 * tg) =
                make_uint2(f2tf(e00), f2tf(e01));
            *(uint2*)(p_s + (rw + g + 8) * 68 + j * 8 + 2 * tg) =
                make_uint2(f2tf(e10), f2tf(e11));
        }
        __syncwarp();   // warp-private P slice

        // ---- MMA2: O[16 x 128] += P . g (conflict-free gT layout) ----------
#pragma unroll
        for (int kc2 = 0; kc2 < 8; ++kc2) {
            uint32_t pa[4];
            pa[0] = p_s[(rw + g) * 68 + kc2 * 8 + tg];
            pa[1] = p_s[(rw + g + 8) * 68 + kc2 * 8 + tg];
            pa[2] = p_s[(rw + g) * 68 + kc2 * 8 + tg + 4];
            pa[3] = p_s[(rw + g + 8) * 68 + kc2 * 8 + tg + 4];
#pragma unroll
            for (int dt = 0; dt < 16; ++dt) {
                uint32_t b0 = g_s[(dt * 8 + g) * 68 + kc2 * 8 + tg];
                uint32_t b1 = g_s[(dt * 8 + g) * 68 + kc2 * 8 + tg + 4];
                mma_tf32(o[dt], pa, b0, b1);
            }
        }
    }

    // ---- finalize: normalize and store y [n][ci] ---------------------------
    l0 += __shfl_xor_sync(0xffffffffu, l0, 1);
    l0 += __shfl_xor_sync(0xffffffffu, l0, 2);
    l1 += __shfl_xor_sync(0xffffffffu, l1, 1);
    l1 += __shfl_xor_sync(0xffffffffu, l1, 2);
    const float inv0 = 1.0f / l0;
    const float inv1 = 1.0f / l1;
    float* yr0 = d_yT + ((size_t)b * HW + n0 + rw + g) * C_I;
    float* yr1 = d_yT + ((size_t)b * HW + n0 + rw + g + 8) * C_I;
#pragma unroll
    for (int dt = 0; dt < 16; ++dt) {
        *(float2*)(yr0 + dt * 8 + 2 * tg) =
            make_float2(o[dt][0] * inv0, o[dt][1] * inv0);
        *(float2*)(yr1 + dt * 8 + 2 * tg) =
            make_float2(o[dt][2] * inv1, o[dt][3] * inv1);
    }
}

// ---------------- kernel 4: W_y conv tf32 mma + bias + residual -------------
// grid (72, 2, 4): x = 128-col tile, y = 128-row out-ch tile, z = batch.
__global__ __launch_bounds__(256, 2) void k_out(
    const float* __restrict__ ww, const float* __restrict__ wb,
    const float* __restrict__ x, float* __restrict__ out)
{
    __shared__ uint32_t Ws[128 * 36];   // [row][k] stride 36
    __shared__ uint32_t Ys[128 * 36];   // [n][k] stride 36 (conflict-free B)

    const int t    = threadIdx.x;
    const int w    = t >> 5;
    const int lane = t & 31;
    const int g    = lane >> 2;
    const int tg   = lane & 3;
    const int rw   = (w & 3) * 32;
    const int cw   = (w >> 2) * 64;
    const int n0   = blockIdx.x * 128;
    const int row0 = blockIdx.y * 128;
    const int b    = blockIdx.z;
    const float* yb = d_yT + (size_t)b * HW * C_I;

    float o[2][8][4];
#pragma unroll
    for (int rt = 0; rt < 2; ++rt)
#pragma unroll
        for (int nt = 0; nt < 8; ++nt) {
            o[rt][nt][0] = 0.f; o[rt][nt][1] = 0.f;
            o[rt][nt][2] = 0.f; o[rt][nt][3] = 0.f;
        }

    for (int k0 = 0; k0 < 128; k0 += 32) {
        __syncthreads();
#pragma unroll
        for (int it = 0; it < 4; ++it) {
            int f4 = t + it * 256;
            int r = f4 >> 3, c = (f4 & 7) * 4;
            float4 v = *(const float4*)(ww + (size_t)(row0 + r) * C_I + k0 + c);
            Ws[r * 36 + c + 0] = f2tf(v.x); Ws[r * 36 + c + 1] = f2tf(v.y);
            Ws[r * 36 + c + 2] = f2tf(v.z); Ws[r * 36 + c + 3] = f2tf(v.w);
        }
#pragma unroll
        for (int it = 0; it < 4; ++it) {
            int f4 = t + it * 256;
            int r = f4 >> 3, c = (f4 & 7) * 4;
            float4 v = *(const float4*)(yb + (size_t)(n0 + r) * C_I + k0 + c);
            Ys[r * 36 + c + 0] = f2tf(v.x); Ys[r * 36 + c + 1] = f2tf(v.y);
            Ys[r * 36 + c + 2] = f2tf(v.z); Ys[r * 36 + c + 3] = f2tf(v.w);
        }
        __syncthreads();
#pragma unroll
        for (int ks = 0; ks < 4; ++ks) {
            uint32_t a[2][4];
#pragma unroll
            for (int rt = 0; rt < 2; ++rt) {
                int rbase = rw + rt * 16 + g;
                a[rt][0] = Ws[rbase * 36 + ks * 8 + tg];
                a[rt][1] = Ws[(rbase + 8) * 36 + ks * 8 + tg];
                a[rt][2] = Ws[rbase * 36 + ks * 8 + tg + 4];
                a[rt][3] = Ws[(rbase + 8) * 36 + ks * 8 + tg + 4];
            }
#pragma unroll
            for (int nt = 0; nt < 8; ++nt) {
                uint32_t b0 = Ys[(cw + nt * 8 + g) * 36 + ks * 8 + tg];
                uint32_t b1 = Ys[(cw + nt * 8 + g) * 36 + ks * 8 + tg + 4];
                mma_tf32(o[0][nt], a[0], b0, b1);
                mma_tf32(o[1][nt], a[1], b0, b1);
            }
        }
    }
    // epilogue: bias + residual
#pragma unroll
    for (int rt = 0; rt < 2; ++rt) {
        int r0 = row0 + rw + rt * 16 + g;
        float bi0 = wb[r0], bi1 = wb[r0 + 8];
        const float* x0 = x + ((size_t)b * C_IN + r0) * HW + n0;
        const float* x1 = x + ((size_t)b * C_IN + r0 + 8) * HW + n0;
        float* o0 = out + ((size_t)b * C_IN + r0) * HW + n0;
        float* o1 = out + ((size_t)b * C_IN + r0 + 8) * HW + n0;
#pragma unroll
        for (int nt = 0; nt < 8; ++nt) {
            int col = cw + nt * 8 + 2 * tg;
            float2 xv0 = *(const float2*)(x0 + col);
            float2 xv1 = *(const float2*)(x1 + col);
            *(float2*)(o0 + col) = make_float2(o[rt][nt][0] + bi0 + xv0.x,
                                               o[rt][nt][1] + bi0 + xv0.y);
            *(float2*)(o1 + col) = make_float2(o[rt][nt][2] + bi1 + xv1.x,
                                               o[rt][nt][3] + bi1 + xv1.y);
        }
    }
}

// ---------------- launch ----------------------------------------------------
extern "C" void kernel_launch(void* const* d_in, const int* in_sizes, int n_in,
                              void* d_out, int out_size)
{
    const float* x  = (const float*)d_in[0];
    const float* gw = (const float*)d_in[1];
    const float* gb = (const float*)d_in[2];
    const float* tw = (const float*)d_in[3];
    const float* tb = (const float*)d_in[4];
    const float* pw = (const float*)d_in[5];
    const float* pb = (const float*)d_in[6];
    const float* ww = (const float*)d_in[7];
    const float* wb = (const float*)d_in[8];
    float* out = (float*)d_out;

    cudaFuncSetAttribute(k_attn, cudaFuncAttributeMaxDynamicSharedMemorySize,
                         ATTN_SMEM_BYTES);

    k_conv3<<<dim3(HW / 128, 3, BATCH), 256>>>(x, gw, gb, tw, tb, pw, pb);
    const int pool_total = 2 * BATCH * C_I * M_VALID;
    k_pool<<<(pool_total + 255) / 256, 256>>>();
    k_attn<<<dim3(HW / TILE_N, BATCH), 256, ATTN_SMEM_BYTES>>>();
    k_out<<<dim3(HW / 128, C_IN / 128, BATCH), 256>>>(ww, wb, x, out);
}

// round 7
// speedup vs baseline: 4.2277x; 1.0879x over previous
#include <cuda_runtime.h>
#include <cstdint>
#include <cstddef>

#define BATCH 4
#define C_IN 256
#define C_I 128
#define HH 96
#define WW 96
#define HW 9216
#define PH 47
#define M_VALID 2209
#define M_PAD 2240
#define N_MTILES 35        // 2240 / 64
#define TILE_N 128
#define TILE_M 64

// ---------------- scratch (device globals; zero-initialized) ----------------
__device__ float d_conv[(size_t)3 * BATCH * C_I * HW];   // [g|theta|phi][b][ci][hw]
__device__ float d_phiT[(size_t)BATCH * M_PAD * C_I];    // [b][m][ci]  (phi pooled)
__device__ float d_gP[(size_t)BATCH * C_I * M_PAD];      // [b][ci][m]  (g pooled)
__device__ float d_yT[(size_t)BATCH * HW * C_I];         // [b][n][ci]

// ---------------- mma.sync helpers (base sm_100 target) ---------------------
__device__ __forceinline__ uint32_t f2tf(float f) {
    uint32_t u;
    asm("cvt.rna.tf32.f32 %0, %1;" : "=r"(u) : "f"(f));
    return u;
}
__device__ __forceinline__ void mma_tf32(float* d, const uint32_t* a,
                                         uint32_t b0, uint32_t b1) {
    asm volatile(
        "mma.sync.aligned.m16n8k8.row.col.f32.tf32.tf32.f32 "
        "{%0,%1,%2,%3}, {%4,%5,%6,%7}, {%8,%9}, {%0,%1,%2,%3};"
        : "+f"(d[0]), "+f"(d[1]), "+f"(d[2]), "+f"(d[3])
        : "r"(a[0]), "r"(a[1]), "r"(a[2]), "r"(a[3]), "r"(b0), "r"(b1));
}
#define BAR_SYNC(id, cnt) \
    asm volatile("bar.sync %0, %1;" :: "r"(id), "r"(cnt) : "memory")
#define BAR_ARRIVE(id, cnt) \
    asm volatile("bar.arrive %0, %1;" :: "r"(id), "r"(cnt) : "memory")

// ---------------- kernel 1: fused g/theta/phi conv, tf32 mma ----------------
__global__ __launch_bounds__(256, 2) void k_conv3(
    const float* __restrict__ x,
    const float* __restrict__ gw, const float* __restrict__ gb,
    const float* __restrict__ tw, const float* __restrict__ tb,
    const float* __restrict__ pw, const float* __restrict__ pb)
{
    __shared__ uint32_t Ws[128 * 36];   // [row][k] stride 36
    __shared__ uint32_t Xs[32 * 128];   // [k][n] stride 128, XOR-swizzled cols

    const int t    = threadIdx.x;
    const int w    = t >> 5;
    const int lane = t & 31;
    const int g    = lane >> 2;
    const int tg   = lane & 3;
    const int rw   = (w & 3) * 32;
    const int cw   = (w >> 2) * 64;
    const int n0   = blockIdx.x * 128;
    const int head = blockIdx.y;
    const int b    = blockIdx.z;
    const float* Wp = (head == 0) ? gw : (head == 1 ? tw : pw);
    const float* Bp = (head == 0) ? gb : (head == 1 ? tb : pb);
    const float* xb = x + (size_t)b * C_IN * HW;

    float o[2][8][4];
#pragma unroll
    for (int rt = 0; rt < 2; ++rt)
#pragma unroll
        for (int nt = 0; nt < 8; ++nt) {
            o[rt][nt][0] = 0.f; o[rt][nt][1] = 0.f;
            o[rt][nt][2] = 0.f; o[rt][nt][3] = 0.f;
        }

    for (int k0 = 0; k0 < 256; k0 += 32) {
        __syncthreads();
#pragma unroll
        for (int it = 0; it < 4; ++it) {
            int f4 = t + it * 256;
            int r = f4 >> 3, c = (f4 & 7) * 4;
            float4 v = *(const float4*)(Wp + (size_t)r * 256 + k0 + c);
            Ws[r * 36 + c + 0] = f2tf(v.x); Ws[r * 36 + c + 1] = f2tf(v.y);
            Ws[r * 36 + c + 2] = f2tf(v.z); Ws[r * 36 + c + 3] = f2tf(v.w);
        }
#pragma unroll
        for (int it = 0; it < 4; ++it) {
            int f4 = t + it * 256;
            int r = f4 >> 5, c = (f4 & 31) * 4;
            int cs = c ^ ((r & 3) << 3);
            float4 v = *(const float4*)(xb + (size_t)(k0 + r) * HW + n0 + c);
            Xs[r * 128 + cs + 0] = f2tf(v.x); Xs[r * 128 + cs + 1] = f2tf(v.y);
            Xs[r * 128 + cs + 2] = f2tf(v.z); Xs[r * 128 + cs + 3] = f2tf(v.w);
        }
        __syncthreads();
#pragma unroll
        for (int ks = 0; ks < 4; ++ks) {
            uint32_t a[2][4];
#pragma unroll
            for (int rt = 0; rt < 2; ++rt) {
                int rbase = rw + rt * 16 + g;
                a[rt][0] = Ws[rbase * 36 + ks * 8 + tg];
                a[rt][1] = Ws[(rbase + 8) * 36 + ks * 8 + tg];
                a[rt][2] = Ws[rbase * 36 + ks * 8 + tg + 4];
                a[rt][3] = Ws[(rbase + 8) * 36 + ks * 8 + tg + 4];
            }
#pragma unroll
            for (int nt = 0; nt < 8; ++nt) {
                int col = (cw + nt * 8 + g) ^ (tg << 3);
                uint32_t b0 = Xs[(ks * 8 + tg) * 128 + col];
                uint32_t b1 = Xs[(ks * 8 + tg + 4) * 128 + col];
                mma_tf32(o[0][nt], a[0], b0, b1);
                mma_tf32(o[1][nt], a[1], b0, b1);
            }
        }
    }
    float* outp = d_conv + ((size_t)(head * BATCH + b) * C_I) * HW;
#pragma unroll
    for (int rt = 0; rt < 2; ++rt) {
        int r0 = rw + rt * 16 + g;
        float bi0 = Bp[r0], bi1 = Bp[r0 + 8];
#pragma unroll
        for (int nt = 0; nt < 8; ++nt) {
            int col = n0 + cw + nt * 8 + 2 * tg;
            *(float2*)(outp + (size_t)r0 * HW + col) =
                make_float2(o[rt][nt][0] + bi0, o[rt][nt][1] + bi0);
            *(float2*)(outp + (size_t)(r0 + 8) * HW + col) =
                make_float2(o[rt][nt][2] + bi1, o[rt][nt][3] + bi1);
        }
    }
}

// ---------------- kernel 2: 3x3/2 maxpool for g and phi ---------------------
__global__ void k_pool()
{
    int idx = blockIdx.x * blockDim.x + threadIdx.x;
    const int total = 2 * BATCH * C_I * M_VALID;
    if (idx >= total) return;
    int m = idx % M_VALID; int r1 = idx / M_VALID;
    int o = r1 % C_I;      int r2 = r1 / C_I;
    int b = r2 % BATCH;    int which = r2 / BATCH;   // 0 = g, 1 = phi
    int slot = which ? 2 : 0;
    const float* src = d_conv + ((size_t)(slot * BATCH + b) * C_I + o) * HW;
    int pr = m / PH, pc = m % PH;
    const float* p = src + (pr * 2) * WW + pc * 2;
    float v = p[0];
    v = fmaxf(v, p[1]); v = fmaxf(v, p[2]);
    v = fmaxf(v, p[WW]); v = fmaxf(v, p[WW + 1]); v = fmaxf(v, p[WW + 2]);
    v = fmaxf(v, p[2 * WW]); v = fmaxf(v, p[2 * WW + 1]); v = fmaxf(v, p[2 * WW + 2]);
    if (which == 0) d_gP[((size_t)b * C_I + o) * M_PAD + m] = v;
    else            d_phiT[((size_t)b * M_PAD + m) * C_I + o] = v;
}

// ---------------- kernel 3: warp-specialized tf32 flash attention -----------
// grid (72, 4), 256 threads. Warps 0-3: MMA1+softmax (32 rows each).
// Warps 4-7: MMA2 (same 32-row slices). Double-buffered phi/g/P.
// smem words: phi[2] 64x132 | g[2] 128x68 | P[2] 128x68
#define PHI_OFS(s) ((s) * 8448)
#define G_OFS(s)   (16896 + (s) * 8704)
#define P_OFS(s)   (34304 + (s) * 8704)
#define ATTN_SMEM_BYTES (51712 * 4)
// named barriers
#define B_PROD  1
#define B_CONS  2
#define B_PRDY(s)  (3 + (s))
#define B_PFREE(s) (5 + (s))

__global__ __launch_bounds__(256, 1) void k_attn()
{
    extern __shared__ uint32_t sm[];
    const int t    = threadIdx.x;
    const int w    = t >> 5;
    const int lane = t & 31;
    const int g    = lane >> 2;
    const int tg   = lane & 3;
    const int b    = blockIdx.y;
    const int n0   = blockIdx.x * TILE_N;

    if (w < 4) {
        // ================= PRODUCERS: MMA1 + softmax =========================
        const int ptid = t;          // 0..127
        const int rw   = w * 32;     // first of 32 query rows
        // theta fragments for 32 rows (2 m-subtiles), held in regs
        uint32_t aF[2][16][4];
        {
            const float* thp =
                d_conv + ((size_t)(1 * BATCH + b) * C_I) * HW + n0 + rw;
#pragma unroll
            for (int mt = 0; mt < 2; ++mt)
#pragma unroll
                for (int kc = 0; kc < 16; ++kc) {
                    const float* p0 = thp + (size_t)(kc * 8 + tg) * HW + mt * 16;
                    const float* p1 = thp + (size_t)(kc * 8 + tg + 4) * HW + mt * 16;
                    aF[mt][kc][0] = f2tf(p0[g]);
                    aF[mt][kc][1] = f2tf(p0[g + 8]);
                    aF[mt][kc][2] = f2tf(p1[g]);
                    aF[mt][kc][3] = f2tf(p1[g + 8]);
                }
        }
        const float* psrc = d_phiT + (size_t)b * M_PAD * C_I;
        // stage phi[0]
        {
            uint32_t* dst = sm + PHI_OFS(0);
#pragma unroll
            for (int it = 0; it < 16; ++it) {
                int f4 = ptid + it * 128;
                int r = f4 >> 5, c = (f4 & 31) * 4;
                float4 v = *(const float4*)(psrc + (size_t)r * C_I + c);
                dst[r * 132 + c + 0] = f2tf(v.x); dst[r * 132 + c + 1] = f2tf(v.y);
                dst[r * 132 + c + 2] = f2tf(v.z); dst[r * 132 + c + 3] = f2tf(v.w);
            }
        }
        BAR_SYNC(B_PROD, 128);

        float off[2][2];
        off[0][0] = 0.f; off[0][1] = 0.f; off[1][0] = 0.f; off[1][1] = 0.f;

        for (int mt_i = 0; mt_i < N_MTILES; ++mt_i) {
            const int s = mt_i & 1;
            // (a) prefetch phi for next tile
            if (mt_i + 1 < N_MTILES) {
                const int m1 = (mt_i + 1) * TILE_M;
                uint32_t* dst = sm + PHI_OFS(1 - s);
#pragma unroll
                for (int it = 0; it < 16; ++it) {
                    int f4 = ptid + it * 128;
                    int r = f4 >> 5, c = (f4 & 31) * 4;
                    float4 v = *(const float4*)(psrc + (size_t)(m1 + r) * C_I + c);
                    dst[r * 132 + c + 0] = f2tf(v.x); dst[r * 132 + c + 1] = f2tf(v.y);
                    dst[r * 132 + c + 2] = f2tf(v.z); dst[r * 132 + c + 3] = f2tf(v.w);
                }
            }
            // (b) MMA1: S[32 x 64]
            const uint32_t* phi_s = sm + PHI_OFS(s);
            float sAcc[2][8][4];
#pragma unroll
            for (int mt = 0; mt < 2; ++mt)
#pragma unroll
                for (int j = 0; j < 8; ++j) {
                    sAcc[mt][j][0] = 0.f; sAcc[mt][j][1] = 0.f;
                    sAcc[mt][j][2] = 0.f; sAcc[mt][j][3] = 0.f;
                }
#pragma unroll
            for (int kc = 0; kc < 16; ++kc)
#pragma unroll
                for (int j = 0; j < 8; ++j) {
                    uint32_t b0 = phi_s[(j * 8 + g) * 132 + kc * 8 + tg];
                    uint32_t b1 = phi_s[(j * 8 + g) * 132 + kc * 8 + tg + 4];
                    mma_tf32(sAcc[0][j], aF[0][kc], b0, b1);
                    mma_tf32(sAcc[1][j], aF[1][kc], b0, b1);
                }
            // (c) softmax (fixed offset from tile-0 sample max)
            if (mt_i == 0) {
#pragma unroll
                for (int mt = 0; mt < 2; ++mt) {
                    float mx0 = sAcc[mt][0][0], mx1 = sAcc[mt][0][2];
#pragma unroll
                    for (int j = 0; j < 8; ++j) {
                        mx0 = fmaxf(mx0, fmaxf(sAcc[mt][j][0], sAcc[mt][j][1]));
                        mx1 = fmaxf(mx1, fmaxf(sAcc[mt][j][2], sAcc[mt][j][3]));
                    }
                    mx0 = fmaxf(mx0, __shfl_xor_sync(0xffffffffu, mx0, 1));
                    mx0 = fmaxf(mx0, __shfl_xor_sync(0xffffffffu, mx0, 2));
                    mx1 = fmaxf(mx1, __shfl_xor_sync(0xffffffffu, mx1, 1));
                    mx1 = fmaxf(mx1, __shfl_xor_sync(0xffffffffu, mx1, 2));
                    off[mt][0] = mx0 + 25.0f;
                    off[mt][1] = mx1 + 25.0f;
                }
            }
            // (d) wait P[s] free (consumed two tiles ago)
            if (mt_i >= 2) BAR_SYNC(B_PFREE(s), 256);
            // (e) exp + write P[s]
            uint32_t* p_s = sm + P_OFS(s);
            const int m0 = mt_i * TILE_M;
            const bool lastt = (mt_i == N_MTILES - 1);
#pragma unroll
            for (int mt = 0; mt < 2; ++mt) {
                const int row = rw + mt * 16;
#pragma unroll
                for (int j = 0; j < 8; ++j) {
                    float e00 = __expf(sAcc[mt][j][0] - off[mt][0]);
                    float e01 = __expf(sAcc[mt][j][1] - off[mt][0]);
                    float e10 = __expf(sAcc[mt][j][2] - off[mt][1]);
                    float e11 = __expf(sAcc[mt][j][3] - off[mt][1]);
                    if (lastt) {
                        int mcol = m0 + j * 8 + 2 * tg;
                        if (mcol >= M_VALID)     { e00 = 0.f; e10 = 0.f; }
                        if (mcol + 1 >= M_VALID) { e01 = 0.f; e11 = 0.f; }
                    }
                    *(uint2*)(p_s + (row + g) * 68 + j * 8 + 2 * tg) =
                        make_uint2(f2tf(e00), f2tf(e01));
                    *(uint2*)(p_s + (row + g + 8) * 68 + j * 8 + 2 * tg) =
                        make_uint2(f2tf(e10), f2tf(e11));
                }
            }
            BAR_ARRIVE(B_PRDY(s), 256);
            // (f) all producers done reading phi[s]
            BAR_SYNC(B_PROD, 128);
        }
    } else {
        // ================= CONSUMERS: MMA2 ===================================
        const int ctid = t - 128;        // 0..127
        const int w2   = w - 4;
        const int rw2  = w2 * 32;
        const float* gsrc = d_gP + (size_t)b * C_I * M_PAD;
        // stage g[0]
        {
            uint32_t* dst = sm + G_OFS(0);
#pragma unroll
            for (int it = 0; it < 16; ++it) {
                int f4 = ctid + it * 128;
                int r = f4 >> 4, c = (f4 & 15) * 4;
                float4 v = *(const float4*)(gsrc + (size_t)r * M_PAD + c);
                dst[r * 68 + c + 0] = f2tf(v.x); dst[r * 68 + c + 1] = f2tf(v.y);
                dst[r * 68 + c + 2] = f2tf(v.z); dst[r * 68 + c + 3] = f2tf(v.w);
            }
        }
        BAR_SYNC(B_CONS, 128);

        float oAcc[2][16][4];
#pragma unroll
        for (int mt = 0; mt < 2; ++mt)
#pragma unroll
            for (int dt = 0; dt < 16; ++dt) {
                oAcc[mt][dt][0] = 0.f; oAcc[mt][dt][1] = 0.f;
                oAcc[mt][dt][2] = 0.f; oAcc[mt][dt][3] = 0.f;
            }
        float lAcc[2][2];
        lAcc[0][0] = 0.f; lAcc[0][1] = 0.f; lAcc[1][0] = 0.f; lAcc[1][1] = 0.f;

        for (int mt_i = 0; mt_i < N_MTILES; ++mt_i) {
            const int s = mt_i & 1;
            // (a) prefetch g for next tile
            if (mt_i + 1 < N_MTILES) {
                const int m1 = (mt_i + 1) * TILE_M;
                uint32_t* dst = sm + G_OFS(1 - s);
#pragma unroll
                for (int it = 0; it < 16; ++it) {
                    int f4 = ctid + it * 128;
                    int r = f4 >> 4, c = (f4 & 15) * 4;
                    float4 v = *(const float4*)(gsrc + (size_t)r * M_PAD + m1 + c);
                    dst[r * 68 + c + 0] = f2tf(v.x); dst[r * 68 + c + 1] = f2tf(v.y);
                    dst[r * 68 + c + 2] = f2tf(v.z); dst[r * 68 + c + 3] = f2tf(v.w);
                }
            }
            // (b) wait P[s]
            BAR_SYNC(B_PRDY(s), 256);
            // (c) MMA2: O[32 x 128] += P . g, plus l accumulation from P frags
            const uint32_t* g_s = sm + G_OFS(s);
            const uint32_t* p_s = sm + P_OFS(s);
#pragma unroll
            for (int kc2 = 0; kc2 < 8; ++kc2) {
                uint32_t pa[2][4];
#pragma unroll
                for (int mt = 0; mt < 2; ++mt) {
                    const int row = rw2 + mt * 16;
                    pa[mt][0] = p_s[(row + g) * 68 + kc2 * 8 + tg];
                    pa[mt][1] = p_s[(row + g + 8) * 68 + kc2 * 8 + tg];
                    pa[mt][2] = p_s[(row + g) * 68 + kc2 * 8 + tg + 4];
                    pa[mt][3] = p_s[(row + g + 8) * 68 + kc2 * 8 + tg + 4];
                    lAcc[mt][0] += __uint_as_float(pa[mt][0]) +
                                   __uint_as_float(pa[mt][2]);
                    lAcc[mt][1] += __uint_as_float(pa[mt][1]) +
                                   __uint_as_float(pa[mt][3]);
                }
#pragma unroll
                for (int dt = 0; dt < 16; ++dt) {
                    uint32_t b0 = g_s[(dt * 8 + g) * 68 + kc2 * 8 + tg];
                    uint32_t b1 = g_s[(dt * 8 + g) * 68 + kc2 * 8 + tg + 4];
                    mma_tf32(oAcc[0][dt], pa[0], b0, b1);
                    mma_tf32(oAcc[1][dt], pa[1], b0, b1);
                }
            }
            // (d) P[s] consumed
            BAR_ARRIVE(B_PFREE(s), 256);
            // (e) all consumers done with g[s]
            BAR_SYNC(B_CONS, 128);
        }

        // finalize: reduce l across the 4 lanes of each row group, store y
#pragma unroll
        for (int mt = 0; mt < 2; ++mt)
#pragma unroll
            for (int h = 0; h < 2; ++h) {
                lAcc[mt][h] += __shfl_xor_sync(0xffffffffu, lAcc[mt][h], 1);
                lAcc[mt][h] += __shfl_xor_sync(0xffffffffu, lAcc[mt][h], 2);
            }
#pragma unroll
        for (int mt = 0; mt < 2; ++mt) {
            const float inv0 = 1.0f / lAcc[mt][0];
            const float inv1 = 1.0f / lAcc[mt][1];
            float* yr0 = d_yT + ((size_t)b * HW + n0 + rw2 + mt * 16 + g) * C_I;
            float* yr1 = yr0 + (size_t)8 * C_I;
#pragma unroll
            for (int dt = 0; dt < 16; ++dt) {
                *(float2*)(yr0 + dt * 8 + 2 * tg) =
                    make_float2(oAcc[mt][dt][0] * inv0, oAcc[mt][dt][1] * inv0);
                *(float2*)(yr1 + dt * 8 + 2 * tg) =
                    make_float2(oAcc[mt][dt][2] * inv1, oAcc[mt][dt][3] * inv1);
            }
        }
    }
}

// ---------------- kernel 4: W_y conv tf32 mma + bias + residual -------------
__global__ __launch_bounds__(256, 2) void k_out(
    const float* __restrict__ ww, const float* __restrict__ wb,
    const float* __restrict__ x, float* __restrict__ out)
{
    __shared__ uint32_t Ws[128 * 36];
    __shared__ uint32_t Ys[128 * 36];

    const int t    = threadIdx.x;
    const int w    = t >> 5;
    const int lane = t & 31;
    const int g    = lane >> 2;
    const int tg   = lane & 3;
    const int rw   = (w & 3) * 32;
    const int cw   = (w >> 2) * 64;
    const int n0   = blockIdx.x * 128;
    const int row0 = blockIdx.y * 128;
    const int b    = blockIdx.z;
    const float* yb = d_yT + (size_t)b * HW * C_I;

    float o[2][8][4];
#pragma unroll
    for (int rt = 0; rt < 2; ++rt)
#pragma unroll
        for (int nt = 0; nt < 8; ++nt) {
            o[rt][nt][0] = 0.f; o[rt][nt][1] = 0.f;
            o[rt][nt][2] = 0.f; o[rt][nt][3] = 0.f;
        }

    for (int k0 = 0; k0 < 128; k0 += 32) {
        __syncthreads();
#pragma unroll
        for (int it = 0; it < 4; ++it) {
            int f4 = t + it * 256;
            int r = f4 >> 3, c = (f4 & 7) * 4;
            float4 v = *(const float4*)(ww + (size_t)(row0 + r) * C_I + k0 + c);
            Ws[r * 36 + c + 0] = f2tf(v.x); Ws[r * 36 + c + 1] = f2tf(v.y);
            Ws[r * 36 + c + 2] = f2tf(v.z); Ws[r * 36 + c + 3] = f2tf(v.w);
        }
#pragma unroll
        for (int it = 0; it < 4; ++it) {
            int f4 = t + it * 256;
            int r = f4 >> 3, c = (f4 & 7) * 4;
            float4 v = *(const float4*)(yb + (size_t)(n0 + r) * C_I + k0 + c);
            Ys[r * 36 + c + 0] = f2tf(v.x); Ys[r * 36 + c + 1] = f2tf(v.y);
            Ys[r * 36 + c + 2] = f2tf(v.z); Ys[r * 36 + c + 3] = f2tf(v.w);
        }
        __syncthreads();
#pragma unroll
        for (int ks = 0; ks < 4; ++ks) {
            uint32_t a[2][4];
#pragma unroll
            for (int rt = 0; rt < 2; ++rt) {
                int rbase = rw + rt * 16 + g;
                a[rt][0] = Ws[rbase * 36 + ks * 8 + tg];
                a[rt][1] = Ws[(rbase + 8) * 36 + ks * 8 + tg];
                a[rt][2] = Ws[rbase * 36 + ks * 8 + tg + 4];
                a[rt][3] = Ws[(rbase + 8) * 36 + ks * 8 + tg + 4];
            }
#pragma unroll
            for (int nt = 0; nt < 8; ++nt) {
                uint32_t b0 = Ys[(cw + nt * 8 + g) * 36 + ks * 8 + tg];
                uint32_t b1 = Ys[(cw + nt * 8 + g) * 36 + ks * 8 + tg + 4];
                mma_tf32(o[0][nt], a[0], b0, b1);
                mma_tf32(o[1][nt], a[1], b0, b1);
            }
        }
    }
#pragma unroll
    for (int rt = 0; rt < 2; ++rt) {
        int r0 = row0 + rw + rt * 16 + g;
        float bi0 = wb[r0], bi1 = wb[r0 + 8];
        const float* x0 = x + ((size_t)b * C_IN + r0) * HW + n0;
        const float* x1 = x + ((size_t)b * C_IN + r0 + 8) * HW + n0;
        float* o0 = out + ((size_t)b * C_IN + r0) * HW + n0;
        float* o1 = out + ((size_t)b * C_IN + r0 + 8) * HW + n0;
#pragma unroll
        for (int nt = 0; nt < 8; ++nt) {
            int col = cw + nt * 8 + 2 * tg;
            float2 xv0 = *(const float2*)(x0 + col);
            float2 xv1 = *(const float2*)(x1 + col);
            *(float2*)(o0 + col) = make_float2(o[rt][nt][0] + bi0 + xv0.x,
                                               o[rt][nt][1] + bi0 + xv0.y);
            *(float2*)(o1 + col) = make_float2(o[rt][nt][2] + bi1 + xv1.x,
                                               o[rt][nt][3] + bi1 + xv1.y);
        }
    }
}

// ---------------- launch ----------------------------------------------------
extern "C" void kernel_launch(void* const* d_in, const int* in_sizes, int n_in,
                              void* d_out, int out_size)
{
    const float* x  = (const float*)d_in[0];
    const float* gw = (const float*)d_in[1];
    const float* gb = (const float*)d_in[2];
    const float* tw = (const float*)d_in[3];
    const float* tb = (const float*)d_in[4];
    const float* pw = (const float*)d_in[5];
    const float* pb = (const float*)d_in[6];
    const float* ww = (const float*)d_in[7];
    const float* wb = (const float*)d_in[8];
    float* out = (float*)d_out;

    cudaFuncSetAttribute(k_attn, cudaFuncAttributeMaxDynamicSharedMemorySize,
                         ATTN_SMEM_BYTES);

    k_conv3<<<dim3(HW / 128, 3, BATCH), 256>>>(x, gw, gb, tw, tb, pw, pb);
    const int pool_total = 2 * BATCH * C_I * M_VALID;
    k_pool<<<(pool_total + 255) / 256, 256>>>();
    k_attn<<<dim3(HW / TILE_N, BATCH), 256, ATTN_SMEM_BYTES>>>();
    k_out<<<dim3(HW / 128, C_IN / 128, BATCH), 256>>>(ww, wb, x, out);
}

// round 8
// speedup vs baseline: 5.8644x; 1.3871x over previous
#include <cuda_runtime.h>
#include <cuda_fp16.h>
#include <cstdint>
#include <cstddef>

#define BATCH 4
#define C_IN 256
#define C_I 128
#define HH 96
#define WW 96
#define HW 9216
#define PH 47
#define M_VALID 2209
#define M_PAD 2240
#define N_MTILES 35        // 2240 / 64
#define TILE_N 128
#define TILE_M 64

// ---------------- scratch (device globals; zero-initialized) ----------------
__device__ float d_conv[(size_t)3 * BATCH * C_I * HW];     // [g|theta|phi][b][ci][hw]
__device__ uint16_t d_phiH[(size_t)BATCH * M_PAD * C_I];   // [b][m][ci]  half
__device__ uint16_t d_gH[(size_t)BATCH * C_I * M_PAD];     // [b][ci][m]  half
__device__ float d_yT[(size_t)BATCH * HW * C_I];           // [b][n][ci]

// ---------------- mma.sync helpers ------------------------------------------
__device__ __forceinline__ uint32_t f2tf(float f) {
    uint32_t u;
    asm("cvt.rna.tf32.f32 %0, %1;" : "=r"(u) : "f"(f));
    return u;
}
__device__ __forceinline__ uint32_t pkh2(float a, float b) {
    __half2 h = __floats2half2_rn(a, b);
    return *(uint32_t*)&h;
}
__device__ __forceinline__ void mma_tf32(float* d, const uint32_t* a,
                                         uint32_t b0, uint32_t b1) {
    asm volatile(
        "mma.sync.aligned.m16n8k8.row.col.f32.tf32.tf32.f32 "
        "{%0,%1,%2,%3}, {%4,%5,%6,%7}, {%8,%9}, {%0,%1,%2,%3};"
        : "+f"(d[0]), "+f"(d[1]), "+f"(d[2]), "+f"(d[3])
        : "r"(a[0]), "r"(a[1]), "r"(a[2]), "r"(a[3]), "r"(b0), "r"(b1));
}
__device__ __forceinline__ void mma_f16(float* d, const uint32_t* a,
                                        uint32_t b0, uint32_t b1) {
    asm volatile(
        "mma.sync.aligned.m16n8k16.row.col.f32.f16.f16.f32 "
        "{%0,%1,%2,%3}, {%4,%5,%6,%7}, {%8,%9}, {%0,%1,%2,%3};"
        : "+f"(d[0]), "+f"(d[1]), "+f"(d[2]), "+f"(d[3])
        : "r"(a[0]), "r"(a[1]), "r"(a[2]), "r"(a[3]), "r"(b0), "r"(b1));
}
#define BAR_SYNC(id, cnt) \
    asm volatile("bar.sync %0, %1;" :: "r"(id), "r"(cnt) : "memory")
#define BAR_ARRIVE(id, cnt) \
    asm volatile("bar.arrive %0, %1;" :: "r"(id), "r"(cnt) : "memory")

// ---------------- kernel 1: fused g/theta/phi conv, tf32 mma ----------------
__global__ __launch_bounds__(256, 2) void k_conv3(
    const float* __restrict__ x,
    const float* __restrict__ gw, const float* __restrict__ gb,
    const float* __restrict__ tw, const float* __restrict__ tb,
    const float* __restrict__ pw, const float* __restrict__ pb)
{
    __shared__ uint32_t Ws[128 * 36];
    __shared__ uint32_t Xs[32 * 128];

    const int t    = threadIdx.x;
    const int w    = t >> 5;
    const int lane = t & 31;
    const int g    = lane >> 2;
    const int tg   = lane & 3;
    const int rw   = (w & 3) * 32;
    const int cw   = (w >> 2) * 64;
    const int n0   = blockIdx.x * 128;
    const int head = blockIdx.y;
    const int b    = blockIdx.z;
    const float* Wp = (head == 0) ? gw : (head == 1 ? tw : pw);
    const float* Bp = (head == 0) ? gb : (head == 1 ? tb : pb);
    const float* xb = x + (size_t)b * C_IN * HW;

    float o[2][8][4];
#pragma unroll
    for (int rt = 0; rt < 2; ++rt)
#pragma unroll
        for (int nt = 0; nt < 8; ++nt) {
            o[rt][nt][0] = 0.f; o[rt][nt][1] = 0.f;
            o[rt][nt][2] = 0.f; o[rt][nt][3] = 0.f;
        }

    for (int k0 = 0; k0 < 256; k0 += 32) {
        __syncthreads();
#pragma unroll
        for (int it = 0; it < 4; ++it) {
            int f4 = t + it * 256;
            int r = f4 >> 3, c = (f4 & 7) * 4;
            float4 v = *(const float4*)(Wp + (size_t)r * 256 + k0 + c);
            Ws[r * 36 + c + 0] = f2tf(v.x); Ws[r * 36 + c + 1] = f2tf(v.y);
            Ws[r * 36 + c + 2] = f2tf(v.z); Ws[r * 36 + c + 3] = f2tf(v.w);
        }
#pragma unroll
        for (int it = 0; it < 4; ++it) {
            int f4 = t + it * 256;
            int r = f4 >> 5, c = (f4 & 31) * 4;
            int cs = c ^ ((r & 3) << 3);
            float4 v = *(const float4*)(xb + (size_t)(k0 + r) * HW + n0 + c);
            Xs[r * 128 + cs + 0] = f2tf(v.x); Xs[r * 128 + cs + 1] = f2tf(v.y);
            Xs[r * 128 + cs + 2] = f2tf(v.z); Xs[r * 128 + cs + 3] = f2tf(v.w);
        }
        __syncthreads();
#pragma unroll
        for (int ks = 0; ks < 4; ++ks) {
            uint32_t a[2][4];
#pragma unroll
            for (int rt = 0; rt < 2; ++rt) {
                int rbase = rw + rt * 16 + g;
                a[rt][0] = Ws[rbase * 36 + ks * 8 + tg];
                a[rt][1] = Ws[(rbase + 8) * 36 + ks * 8 + tg];
                a[rt][2] = Ws[rbase * 36 + ks * 8 + tg + 4];
                a[rt][3] = Ws[(rbase + 8) * 36 + ks * 8 + tg + 4];
            }
#pragma unroll
            for (int nt = 0; nt < 8; ++nt) {
                int col = (cw + nt * 8 + g) ^ (tg << 3);
                uint32_t b0 = Xs[(ks * 8 + tg) * 128 + col];
                uint32_t b1 = Xs[(ks * 8 + tg + 4) * 128 + col];
                mma_tf32(o[0][nt], a[0], b0, b1);
                mma_tf32(o[1][nt], a[1], b0, b1);
            }
        }
    }
    float* outp = d_conv + ((size_t)(head * BATCH + b) * C_I) * HW;
#pragma unroll
    for (int rt = 0; rt < 2; ++rt) {
        int r0 = rw + rt * 16 + g;
        float bi0 = Bp[r0], bi1 = Bp[r0 + 8];
#pragma unroll
        for (int nt = 0; nt < 8; ++nt) {
            int col = n0 + cw + nt * 8 + 2 * tg;
            *(float2*)(outp + (size_t)r0 * HW + col) =
                make_float2(o[rt][nt][0] + bi0, o[rt][nt][1] + bi0);
            *(float2*)(outp + (size_t)(r0 + 8) * HW + col) =
                make_float2(o[rt][nt][2] + bi1, o[rt][nt][3] + bi1);
        }
    }
}

// ---------------- kernel 2: 3x3/2 maxpool for g and phi (fp32 -> half) ------
__global__ void k_pool()
{
    int idx = blockIdx.x * blockDim.x + threadIdx.x;
    const int total = 2 * BATCH * C_I * M_VALID;
    if (idx >= total) return;
    int m = idx % M_VALID; int r1 = idx / M_VALID;
    int o = r1 % C_I;      int r2 = r1 / C_I;
    int b = r2 % BATCH;    int which = r2 / BATCH;   // 0 = g, 1 = phi
    int slot = which ? 2 : 0;
    const float* src = d_conv + ((size_t)(slot * BATCH + b) * C_I + o) * HW;
    int pr = m / PH, pc = m % PH;
    const float* p = src + (pr * 2) * WW + pc * 2;
    float v = p[0];
    v = fmaxf(v, p[1]); v = fmaxf(v, p[2]);
    v = fmaxf(v, p[WW]); v = fmaxf(v, p[WW + 1]); v = fmaxf(v, p[WW + 2]);
    v = fmaxf(v, p[2 * WW]); v = fmaxf(v, p[2 * WW + 1]); v = fmaxf(v, p[2 * WW + 2]);
    uint16_t h = __half_as_ushort(__float2half_rn(v));
    if (which == 0) d_gH[((size_t)b * C_I + o) * M_PAD + m] = h;
    else            d_phiH[((size_t)b * M_PAD + m) * C_I + o] = h;
}

// ---------------- kernel 3: warp-specialized fp16 flash attention -----------
// grid (72, 4), 256 threads. Warps 0-3: MMA1+softmax. Warps 4-7: MMA2.
// smem words: phi[2] 64x68 | g[2] 128x68 | P[2] 128x36 | alpha[2] 128 | l 128
#define PHI_OFS(s) ((s) * 4352)
#define G_OFS(s)   (8704 + (s) * 8704)
#define P_OFS(s)   (26112 + (s) * 4608)
#define A_OFS(s)   (35328 + (s) * 128)
#define L_OFS      35584
#define ATTN_SMEM_BYTES ((35584 + 128) * 4)
#define B_PROD  1
#define B_CONS  2
#define B_PRDY(s)  (3 + (s))
#define B_PFREE(s) (5 + (s))

__global__ __launch_bounds__(256, 1) void k_attn()
{
    extern __shared__ uint32_t sm[];
    float* smf = (float*)sm;
    const int t    = threadIdx.x;
    const int w    = t >> 5;
    const int lane = t & 31;
    const int g    = lane >> 2;
    const int tg   = lane & 3;
    const int b    = blockIdx.y;
    const int n0   = blockIdx.x * TILE_N;

    if (w < 4) {
        // ================= PRODUCERS: MMA1 + softmax =========================
        const int ptid = t;
        const int rw   = w * 32;
        // theta fragments: fp16 packed pairs along k; held in regs whole loop
        uint32_t aF[2][8][4];
        {
            const float* thp =
                d_conv + ((size_t)(1 * BATCH + b) * C_I) * HW + n0 + rw;
#pragma unroll
            for (int mt = 0; mt < 2; ++mt) {
                const int nlo = mt * 16 + g;
#pragma unroll
                for (int kc = 0; kc < 8; ++kc) {
                    const float* c0 = thp + (size_t)(kc * 16 + 2 * tg) * HW;
                    const float* c1 = c0 + HW;
                    const float* c2 = thp + (size_t)(kc * 16 + 2 * tg + 8) * HW;
                    const float* c3 = c2 + HW;
                    aF[mt][kc][0] = pkh2(c0[nlo], c1[nlo]);
                    aF[mt][kc][1] = pkh2(c0[nlo + 8], c1[nlo + 8]);
                    aF[mt][kc][2] = pkh2(c2[nlo], c3[nlo]);
                    aF[mt][kc][3] = pkh2(c2[nlo + 8], c3[nlo + 8]);
                }
            }
        }
        const uint16_t* psrc = d_phiH + (size_t)b * M_PAD * C_I;
        // stage phi[0]: 64 rows x 128 halves
        {
#pragma unroll
            for (int it = 0; it < 8; ++it) {
                int f4 = ptid + it * 128;
                int r = f4 >> 4, c8 = f4 & 15;
                uint4 v = *(const uint4*)(psrc + (size_t)r * C_I + c8 * 8);
                *(uint4*)(sm + PHI_OFS(0) + r * 68 + c8 * 4) = v;
            }
        }
        BAR_SYNC(B_PROD, 128);

        float mrun[2][2], lA[2][2];
#pragma unroll
        for (int mt = 0; mt < 2; ++mt) {
            mrun[mt][0] = -1e30f; mrun[mt][1] = -1e30f;
            lA[mt][0] = 0.f; lA[mt][1] = 0.f;
        }

        for (int mt_i = 0; mt_i < N_MTILES; ++mt_i) {
            const int s = mt_i & 1;
            if (mt_i + 1 < N_MTILES) {
                const int m1 = (mt_i + 1) * TILE_M;
#pragma unroll
                for (int it = 0; it < 8; ++it) {
                    int f4 = ptid + it * 128;
                    int r = f4 >> 4, c8 = f4 & 15;
                    uint4 v = *(const uint4*)(psrc + (size_t)(m1 + r) * C_I + c8 * 8);
                    *(uint4*)(sm + PHI_OFS(1 - s) + r * 68 + c8 * 4) = v;
                }
            }
            // MMA1: S[32 x 64]
            const uint32_t* phi_s = sm + PHI_OFS(s);
            float sA[2][8][4];
#pragma unroll
            for (int mt = 0; mt < 2; ++mt)
#pragma unroll
                for (int j = 0; j < 8; ++j) {
                    sA[mt][j][0] = 0.f; sA[mt][j][1] = 0.f;
                    sA[mt][j][2] = 0.f; sA[mt][j][3] = 0.f;
                }
#pragma unroll
            for (int kc = 0; kc < 8; ++kc)
#pragma unroll
                for (int j = 0; j < 8; ++j) {
                    uint32_t b0 = phi_s[(j * 8 + g) * 68 + kc * 8 + tg];
                    uint32_t b1 = phi_s[(j * 8 + g) * 68 + kc * 8 + tg + 4];
                    mma_f16(sA[0][j], aF[0][kc], b0, b1);
                    mma_f16(sA[1][j], aF[1][kc], b0, b1);
                }
            // per-tile row max -> lazy rescale factors
            float al[2][2];
#pragma unroll
            for (int mt = 0; mt < 2; ++mt) {
                float mx0 = sA[mt][0][0], mx1 = sA[mt][0][2];
#pragma unroll
                for (int j = 0; j < 8; ++j) {
                    mx0 = fmaxf(mx0, fmaxf(sA[mt][j][0], sA[mt][j][1]));
                    mx1 = fmaxf(mx1, fmaxf(sA[mt][j][2], sA[mt][j][3]));
                }
                mx0 = fmaxf(mx0, __shfl_xor_sync(0xffffffffu, mx0, 1));
                mx0 = fmaxf(mx0, __shfl_xor_sync(0xffffffffu, mx0, 2));
                mx1 = fmaxf(mx1, __shfl_xor_sync(0xffffffffu, mx1, 1));
                mx1 = fmaxf(mx1, __shfl_xor_sync(0xffffffffu, mx1, 2));
                if (mx0 > mrun[mt][0]) {
                    al[mt][0] = __expf(mrun[mt][0] - mx0); mrun[mt][0] = mx0;
                } else al[mt][0] = 1.f;
                if (mx1 > mrun[mt][1]) {
                    al[mt][1] = __expf(mrun[mt][1] - mx1); mrun[mt][1] = mx1;
                } else al[mt][1] = 1.f;
                lA[mt][0] *= al[mt][0];
                lA[mt][1] *= al[mt][1];
            }
            // wait P[s] free (consumed two tiles ago)
            if (mt_i >= 2) BAR_SYNC(B_PFREE(s), 256);
            // publish alphas
            if (tg == 0) {
#pragma unroll
                for (int mt = 0; mt < 2; ++mt) {
                    smf[A_OFS(s) + rw + mt * 16 + g]     = al[mt][0];
                    smf[A_OFS(s) + rw + mt * 16 + g + 8] = al[mt][1];
                }
            }
            // exp (scaled x256) + pack half2 + accumulate l + write P
            uint32_t* p_s = sm + P_OFS(s);
            const int m0 = mt_i * TILE_M;
            const bool lastt = (mt_i == N_MTILES - 1);
#pragma unroll
            for (int mt = 0; mt < 2; ++mt) {
                const int row = rw + mt * 16;
#pragma unroll
                for (int j = 0; j < 8; ++j) {
                    float e00 = __expf(sA[mt][j][0] - mrun[mt][0]);
                    float e01 = __expf(sA[mt][j][1] - mrun[mt][0]);
                    float e10 = __expf(sA[mt][j][2] - mrun[mt][1]);
                    float e11 = __expf(sA[mt][j][3] - mrun[mt][1]);
                    if (lastt) {
                        int mcol = m0 + j * 8 + 2 * tg;
                        if (mcol >= M_VALID)     { e00 = 0.f; e10 = 0.f; }
                        if (mcol + 1 >= M_VALID) { e01 = 0.f; e11 = 0.f; }
                    }
                    lA[mt][0] += e00 + e01;
                    lA[mt][1] += e10 + e11;
                    p_s[(row + g) * 36 + j * 4 + tg] =
                        pkh2(e00 * 256.f, e01 * 256.f);
                    p_s[(row + g + 8) * 36 + j * 4 + tg] =
                        pkh2(e10 * 256.f, e11 * 256.f);
                }
            }
            if (lastt) {
                // final l: reduce over tg lanes, publish
#pragma unroll
                for (int mt = 0; mt < 2; ++mt)
#pragma unroll
                    for (int h = 0; h < 2; ++h) {
                        lA[mt][h] += __shfl_xor_sync(0xffffffffu, lA[mt][h], 1);
                        lA[mt][h] += __shfl_xor_sync(0xffffffffu, lA[mt][h], 2);
                    }
                if (tg == 0) {
#pragma unroll
                    for (int mt = 0; mt < 2; ++mt) {
                        smf[L_OFS + rw + mt * 16 + g]     = lA[mt][0];
                        smf[L_OFS + rw + mt * 16 + g + 8] = lA[mt][1];
                    }
                }
            }
            BAR_ARRIVE(B_PRDY(s), 256);
            BAR_SYNC(B_PROD, 128);
        }
    } else {
        // ================= CONSUMERS: MMA2 ===================================
        const int ctid = t - 128;
        const int w2   = w - 4;
        const int rw2  = w2 * 32;
        const uint16_t* gsrc = d_gH + (size_t)b * C_I * M_PAD;
        // stage g[0]: 128 rows x 64 halves
        {
#pragma unroll
            for (int it = 0; it < 8; ++it) {
                int f4 = ctid + it * 128;
                int r = f4 >> 3, c8 = f4 & 7;
                uint4 v = *(const uint4*)(gsrc + (size_t)r * M_PAD + c8 * 8);
                *(uint4*)(sm + G_OFS(0) + r * 68 + c8 * 4) = v;
            }
        }
        BAR_SYNC(B_CONS, 128);

        float oA[2][16][4];
#pragma unroll
        for (int mt = 0; mt < 2; ++mt)
#pragma unroll
            for (int dt = 0; dt < 16; ++dt) {
                oA[mt][dt][0] = 0.f; oA[mt][dt][1] = 0.f;
                oA[mt][dt][2] = 0.f; oA[mt][dt][3] = 0.f;
            }

        for (int mt_i = 0; mt_i < N_MTILES; ++mt_i) {
            const int s = mt_i & 1;
            if (mt_i + 1 < N_MTILES) {
                const int m1 = (mt_i + 1) * TILE_M;
#pragma unroll
                for (int it = 0; it < 8; ++it) {
                    int f4 = ctid + it * 128;
                    int r = f4 >> 3, c8 = f4 & 7;
                    uint4 v = *(const uint4*)(gsrc + (size_t)r * M_PAD + m1 + c8 * 8);
                    *(uint4*)(sm + G_OFS(1 - s) + r * 68 + c8 * 4) = v;
                }
            }
            BAR_SYNC(B_PRDY(s), 256);
            // lazy O rescale (rare: only when a row max was raised)
            {
                float a00 = smf[A_OFS(s) + rw2 + g];
                float a01 = smf[A_OFS(s) + rw2 + g + 8];
                float a10 = smf[A_OFS(s) + rw2 + 16 + g];
                float a11 = smf[A_OFS(s) + rw2 + 16 + g + 8];
                float mn = fminf(fminf(a00, a01), fminf(a10, a11));
                if (__any_sync(0xffffffffu, mn < 1.f)) {
#pragma unroll
                    for (int dt = 0; dt < 16; ++dt) {
                        oA[0][dt][0] *= a00; oA[0][dt][1] *= a00;
                        oA[0][dt][2] *= a01; oA[0][dt][3] *= a01;
                        oA[1][dt][0] *= a10; oA[1][dt][1] *= a10;
                        oA[1][dt][2] *= a11; oA[1][dt][3] *= a11;
                    }
                }
            }
            // MMA2: O[32 x 128] += P . g
            const uint32_t* g_s = sm + G_OFS(s);
            const uint32_t* p_s = sm + P_OFS(s);
#pragma unroll
            for (int kc2 = 0; kc2 < 4; ++kc2) {
                uint32_t pa[2][4];
#pragma unroll
                for (int mt = 0; mt < 2; ++mt) {
                    const int row = rw2 + mt * 16;
                    pa[mt][0] = p_s[(row + g) * 36 + kc2 * 8 + tg];
                    pa[mt][1] = p_s[(row + g + 8) * 36 + kc2 * 8 + tg];
                    pa[mt][2] = p_s[(row + g) * 36 + kc2 * 8 + tg + 4];
                    pa[mt][3] = p_s[(row + g + 8) * 36 + kc2 * 8 + tg + 4];
                }
#pragma unroll
                for (int dt = 0; dt < 16; ++dt) {
                    uint32_t b0 = g_s[(dt * 8 + g) * 68 + kc2 * 8 + tg];
                    uint32_t b1 = g_s[(dt * 8 + g) * 68 + kc2 * 8 + tg + 4];
                    mma_f16(oA[0][dt], pa[0], b0, b1);
                    mma_f16(oA[1][dt], pa[1], b0, b1);
                }
            }
            BAR_ARRIVE(B_PFREE(s), 256);
            BAR_SYNC(B_CONS, 128);
        }

        // finalize: read l, normalize (incl. the x256 P scale), store y
#pragma unroll
        for (int mt = 0; mt < 2; ++mt) {
            const float l0 = smf[L_OFS + rw2 + mt * 16 + g];
            const float l1 = smf[L_OFS + rw2 + mt * 16 + g + 8];
            const float inv0 = 1.0f / (256.f * l0);
            const float inv1 = 1.0f / (256.f * l1);
            float* yr0 = d_yT + ((size_t)b * HW + n0 + rw2 + mt * 16 + g) * C_I;
            float* yr1 = yr0 + (size_t)8 * C_I;
#pragma unroll
            for (int dt = 0; dt < 16; ++dt) {
                *(float2*)(yr0 + dt * 8 + 2 * tg) =
                    make_float2(oA[mt][dt][0] * inv0, oA[mt][dt][1] * inv0);
                *(float2*)(yr1 + dt * 8 + 2 * tg) =
                    make_float2(oA[mt][dt][2] * inv1, oA[mt][dt][3] * inv1);
            }
        }
    }
}

// ---------------- kernel 4: W_y conv tf32 mma + bias + residual -------------
__global__ __launch_bounds__(256, 2) void k_out(
    const float* __restrict__ ww, const float* __restrict__ wb,
    const float* __restrict__ x, float* __restrict__ out)
{
    __shared__ uint32_t Ws[128 * 36];
    __shared__ uint32_t Ys[128 * 36];

    const int t    = threadIdx.x;
    const int w    = t >> 5;
    const int lane = t & 31;
    const int g    = lane >> 2;
    const int tg   = lane & 3;
    const int rw   = (w & 3) * 32;
    const int cw   = (w >> 2) * 64;
    const int n0   = blockIdx.x * 128;
    const int row0 = blockIdx.y * 128;
    const int b    = blockIdx.z;
    const float* yb = d_yT + (size_t)b * HW * C_I;

    float o[2][8][4];
#pragma unroll
    for (int rt = 0; rt < 2; ++rt)
#pragma unroll
        for (int nt = 0; nt < 8; ++nt) {
            o[rt][nt][0] = 0.f; o[rt][nt][1] = 0.f;
            o[rt][nt][2] = 0.f; o[rt][nt][3] = 0.f;
        }

    for (int k0 = 0; k0 < 128; k0 += 32) {
        __syncthreads();
#pragma unroll
        for (int it = 0; it < 4; ++it) {
            int f4 = t + it * 256;
            int r = f4 >> 3, c = (f4 & 7) * 4;
            float4 v = *(const float4*)(ww + (size_t)(row0 + r) * C_I + k0 + c);
            Ws[r * 36 + c + 0] = f2tf(v.x); Ws[r * 36 + c + 1] = f2tf(v.y);
            Ws[r * 36 + c + 2] = f2tf(v.z); Ws[r * 36 + c + 3] = f2tf(v.w);
        }
#pragma unroll
        for (int it = 0; it < 4; ++it) {
            int f4 = t + it * 256;
            int r = f4 >> 3, c = (f4 & 7) * 4;
            float4 v = *(const float4*)(yb + (size_t)(n0 + r) * C_I + k0 + c);
            Ys[r * 36 + c + 0] = f2tf(v.x); Ys[r * 36 + c + 1] = f2tf(v.y);
            Ys[r * 36 + c + 2] = f2tf(v.z); Ys[r * 36 + c + 3] = f2tf(v.w);
        }
        __syncthreads();
#pragma unroll
        for (int ks = 0; ks < 4; ++ks) {
            uint32_t a[2][4];
#pragma unroll
            for (int rt = 0; rt < 2; ++rt) {
                int rbase = rw + rt * 16 + g;
                a[rt][0] = Ws[rbase * 36 + ks * 8 + tg];
                a[rt][1] = Ws[(rbase + 8) * 36 + ks * 8 + tg];
                a[rt][2] = Ws[rbase * 36 + ks * 8 + tg + 4];
                a[rt][3] = Ws[(rbase + 8) * 36 + ks * 8 + tg + 4];
            }
#pragma unroll
            for (int nt = 0; nt < 8; ++nt) {
                uint32_t b0 = Ys[(cw + nt * 8 + g) * 36 + ks * 8 + tg];
                uint32_t b1 = Ys[(cw + nt * 8 + g) * 36 + ks * 8 + tg + 4];
                mma_tf32(o[0][nt], a[0], b0, b1);
                mma_tf32(o[1][nt], a[1], b0, b1);
            }
        }
    }
#pragma unroll
    for (int rt = 0; rt < 2; ++rt) {
        int r0 = row0 + rw + rt * 16 + g;
        float bi0 = wb[r0], bi1 = wb[r0 + 8];
        const float* x0 = x + ((size_t)b * C_IN + r0) * HW + n0;
        const float* x1 = x + ((size_t)b * C_IN + r0 + 8) * HW + n0;
        float* o0 = out + ((size_t)b * C_IN + r0) * HW + n0;
        float* o1 = out + ((size_t)b * C_IN + r0 + 8) * HW + n0;
#pragma unroll
        for (int nt = 0; nt < 8; ++nt) {
            int col = cw + nt * 8 + 2 * tg;
            float2 xv0 = *(const float2*)(x0 + col);
            float2 xv1 = *(const float2*)(x1 + col);
            *(float2*)(o0 + col) = make_float2(o[rt][nt][0] + bi0 + xv0.x,
                                               o[rt][nt][1] + bi0 + xv0.y);
            *(float2*)(o1 + col) = make_float2(o[rt][nt][2] + bi1 + xv1.x,
                                               o[rt][nt][3] + bi1 + xv1.y);
        }
    }
}

// ---------------- launch ----------------------------------------------------
extern "C" void kernel_launch(void* const* d_in, const int* in_sizes, int n_in,
                              void* d_out, int out_size)
{
    const float* x  = (const float*)d_in[0];
    const float* gw = (const float*)d_in[1];
    const float* gb = (const float*)d_in[2];
    const float* tw = (const float*)d_in[3];
    const float* tb = (const float*)d_in[4];
    const float* pw = (const float*)d_in[5];
    const float* pb = (const float*)d_in[6];
    const float* ww = (const float*)d_in[7];
    const float* wb = (const float*)d_in[8];
    float* out = (float*)d_out;

    cudaFuncSetAttribute(k_attn, cudaFuncAttributeMaxDynamicSharedMemorySize,
                         ATTN_SMEM_BYTES);

    k_conv3<<<dim3(HW / 128, 3, BATCH), 256>>>(x, gw, gb, tw, tb, pw, pb);
    const int pool_total = 2 * BATCH * C_I * M_VALID;
    k_pool<<<(pool_total + 255) / 256, 256>>>();
    k_attn<<<dim3(HW / TILE_N, BATCH), 256, ATTN_SMEM_BYTES>>>();
    k_out<<<dim3(HW / 128, C_IN / 128, BATCH), 256>>>(ww, wb, x, out);
}